// round 12
// baseline (speedup 1.0000x reference)
#include <cuda_runtime.h>
#include <cstdint>

#define N_NODES 1024
#define F_DIM   1024
#define H_DIM   512
#define E_EDGES 32768
#define B_GRAPHS 16
#define OUT_DIM 10
#define Z_DIM   (F_DIM + H_DIM)   // 1536
#define EPSB    1e-5f
#define MH_Cf   0.8673250705840776f
#define NEG_HALF_LOG2E (-0.7213475204444817f)
#define LOG2E   1.4426950408889634f
#define INV_SQRT2 0.7071067811865476f
#define RN 16                      // nodes per wavbase block
#define NPAIR (RN / 2)             // 8
#define SPLIT 8                    // i-dimension split factor
#define ISPLIT (H_DIM / SPLIT)     // 64 i's per block

// ---------------- scratch (static device memory; no allocations) ----------------
__device__ __align__(16) float  d_h   [N_NODES * H_DIM];
__device__ __align__(16) float  d_agg [N_NODES * H_DIM];
__device__ __align__(16) float4 d_wpack[H_DIM * H_DIM];   // [i][o] = {invS, -T*invS, C*Wwav, Wbase}
__device__ __align__(16) float  d_partial[SPLIT * N_NODES * H_DIM]; // wav+base partials
__device__ float d_mu [Z_DIM];
__device__ float d_sc [Z_DIM];
__device__ float d_gsum[B_GRAPHS * Z_DIM];
__device__ float d_h1 [B_GRAPHS * 512];
// CSR scratch
__device__ int d_off [N_NODES + 1];
__device__ int d_elist[E_EDGES];
__device__ int d_roff[B_GRAPHS + 1];   // per-graph node ranges (batch is sorted)

__device__ __forceinline__ float ex2f(float x) {
    float r; asm("ex2.approx.ftz.f32 %0, %1;" : "=f"(r) : "f"(x)); return r;
}
__device__ __forceinline__ float fsigmoid(float t) {
    return 1.0f / (1.0f + ex2f(-t * LOG2E));
}

// ---- f32x2 packed-math helpers (sm_103a) ----
typedef unsigned long long u64;
__device__ __forceinline__ u64 pack2(float lo, float hi) {
    u64 r; asm("mov.b64 %0, {%1, %2};" : "=l"(r) : "f"(lo), "f"(hi)); return r;
}
__device__ __forceinline__ void unpack2(u64 v, float& lo, float& hi) {
    asm("mov.b64 {%0, %1}, %2;" : "=f"(lo), "=f"(hi) : "l"(v));
}
__device__ __forceinline__ u64 fma2(u64 a, u64 b, u64 c) {
    u64 d; asm("fma.rn.f32x2 %0, %1, %2, %3;" : "=l"(d) : "l"(a), "l"(b), "l"(c)); return d;
}
__device__ __forceinline__ u64 mul2(u64 a, u64 b) {
    u64 d; asm("mul.rn.f32x2 %0, %1, %2;" : "=l"(d) : "l"(a), "l"(b)); return d;
}

// =================================================================================
// 1. setup (1024-thread blocks):
//    blocks [0,255]   : wpack
//    blocks [256,767] : h
//    block  768       : CSR build (deg -> warp-shuffle scan -> fill)
//    block  769       : graph ranges
// =================================================================================
__global__ void __launch_bounds__(1024) k_setup(
        const float* __restrict__ x,      const float* __restrict__ watt,
        const float* __restrict__ scale,  const float* __restrict__ trans,
        const float* __restrict__ wavw,   const float* __restrict__ basew,
        const int*   __restrict__ ei,     const int*   __restrict__ batch) {
    int blk = blockIdx.x, t = threadIdx.x;

    if (blk < 256) {                                // ---- wpack ----
        int idx = blk * 1024 + t;                   // idx = o*512 + i
        int o = idx >> 9, i = idx & 511;
        float invS = 1.0f / scale[idx];
        d_wpack[i * H_DIM + o] = make_float4(invS, -trans[idx] * invS,
                                             MH_Cf * wavw[idx], basew[idx]);
        return;
    }
    if (blk < 768) {                                // ---- h ----
        int idx = (blk - 256) * 1024 + t;           // n*H + j
        int n = idx >> 9, j = idx & 511;
        float2 p = reinterpret_cast<const float2*>(x)[n * (F_DIM / 2) + j];
        float lo = (p.x + p.y) * INV_SQRT2;
        float hi = (p.x - p.y) * INV_SQRT2;
        float s  = fsigmoid(lo * watt[0] + hi * watt[1]);
        d_h[idx] = hi + s * (lo - hi);
        return;
    }
    if (blk == 768) {                               // ---- CSR build ----
        __shared__ int s[N_NODES];
        __shared__ int wsum[32];
        s[t] = 0;
        __syncthreads();
        for (int e = t; e < E_EDGES; e += 1024)
            atomicAdd(&s[ei[E_EDGES + e]], 1);
        __syncthreads();
        int v = s[t];
        int lane = t & 31, wid = t >> 5;
        int inc = v;
#pragma unroll
        for (int d = 1; d < 32; d <<= 1) {
            int up = __shfl_up_sync(0xffffffffu, inc, d);
            if (lane >= d) inc += up;
        }
        if (lane == 31) wsum[wid] = inc;
        __syncthreads();
        if (wid == 0) {
            int wv = wsum[lane];
            int winc = wv;
#pragma unroll
            for (int d = 1; d < 32; d <<= 1) {
                int up = __shfl_up_sync(0xffffffffu, winc, d);
                if (lane >= d) winc += up;
            }
            wsum[lane] = winc - wv;                 // exclusive warp offsets
        }
        __syncthreads();
        int excl = wsum[wid] + inc - v;
        d_off[t] = excl;
        if (t == N_NODES - 1) d_off[N_NODES] = excl + v;
        __syncthreads();
        s[t] = excl;                                // fill cursors
        __syncthreads();
        for (int e = t; e < E_EDGES; e += 1024) {
            int dst = ei[E_EDGES + e];
            int pos = atomicAdd(&s[dst], 1);
            d_elist[pos] = ei[e];
        }
        return;
    }
    {                                               // ---- graph ranges ----
        __shared__ int rs[B_GRAPHS + 1];
        if (t <= B_GRAPHS) rs[t] = -1;
        __syncthreads();
        for (int n = t; n < N_NODES; n += 1024) {
            int b = batch[n];
            if (n == 0 || batch[n - 1] != b) rs[b] = n;
        }
        __syncthreads();
        if (t == 0) {
            rs[B_GRAPHS] = N_NODES;
            for (int b = B_GRAPHS - 1; b >= 0; b--)
                if (rs[b] < 0) rs[b] = rs[b + 1];
            for (int b = 0; b <= B_GRAPHS; b++) d_roff[b] = rs[b];
        }
    }
}

// =================================================================================
// 2. stats over x columns:
//    blocks [0,31]  : colstats -> d_mu, d_sc for j in [0,1024)
//    blocks [32,95] : pool sums (16 graphs x 4 chunks, atomic-free)
// =================================================================================
__global__ void __launch_bounds__(256) k_stats_x(const float* __restrict__ x) {
    int blk = blockIdx.x, t = threadIdx.x;
    if (blk < 32) {                                   // ---- colstats (x) ----
        __shared__ float ssum[8][32], ssq[8][32];
        int c = t & 31, r = t >> 5;
        int j = blk * 32 + c;
        float s = 0.0f, q = 0.0f;
        for (int n = r; n < N_NODES; n += 8) {
            float v = x[n * F_DIM + j];
            s += v; q = fmaf(v, v, q);
        }
        ssum[r][c] = s; ssq[r][c] = q;
        __syncthreads();
        if (r == 0) {
#pragma unroll
            for (int rr = 1; rr < 8; rr++) { s += ssum[rr][c]; q += ssq[rr][c]; }
            float mu  = s * (1.0f / N_NODES);
            float var = fmaxf(q * (1.0f / N_NODES) - mu * mu, 0.0f);
            d_mu[j] = mu;
            d_sc[j] = rsqrtf(var + EPSB);
        }
        return;
    }
    {                                                 // ---- pool sums (x) ----
        int w   = blk - 32;                           // 0..63
        int b   = w >> 2;
        int ch  = w & 3;
        int j   = ch * 256 + t;
        int beg = d_roff[b], end = d_roff[b + 1];
        float s = 0.0f;
        int n = beg;
        for (; n + 4 <= end; n += 4) {
            float v0 = x[n * F_DIM + j];
            float v1 = x[(n + 1) * F_DIM + j];
            float v2 = x[(n + 2) * F_DIM + j];
            float v3 = x[(n + 3) * F_DIM + j];
            s += (v0 + v1) + (v2 + v3);
        }
        for (; n < end; n++) s += x[n * F_DIM + j];
        d_gsum[b * Z_DIM + j] = s;
    }
}

// =================================================================================
// 3. gather: agg[n] = h[n] + sum_{e: dst=n} h[src]
// =================================================================================
__global__ void __launch_bounds__(128) k_gather() {
    __shared__ int se[128];
    int n = blockIdx.x, t = threadIdx.x;
    int beg = d_off[n], end = d_off[n + 1];
    float4 acc = reinterpret_cast<const float4*>(d_h + n * H_DIM)[t];
    for (int t0 = beg; t0 < end; t0 += 128) {
        int cnt = min(128, end - t0);
        if (t < cnt) se[t] = d_elist[t0 + t];
        __syncthreads();
        int k = 0;
        for (; k + 4 <= cnt; k += 4) {
            float4 v0 = reinterpret_cast<const float4*>(d_h + se[k]     * H_DIM)[t];
            float4 v1 = reinterpret_cast<const float4*>(d_h + se[k + 1] * H_DIM)[t];
            float4 v2 = reinterpret_cast<const float4*>(d_h + se[k + 2] * H_DIM)[t];
            float4 v3 = reinterpret_cast<const float4*>(d_h + se[k + 3] * H_DIM)[t];
            acc.x += v0.x + v1.x + v2.x + v3.x;
            acc.y += v0.y + v1.y + v2.y + v3.y;
            acc.z += v0.z + v1.z + v2.z + v3.z;
            acc.w += v0.w + v1.w + v2.w + v3.w;
        }
        for (; k < cnt; k++) {
            float4 v = reinterpret_cast<const float4*>(d_h + se[k] * H_DIM)[t];
            acc.x += v.x; acc.y += v.y; acc.z += v.z; acc.w += v.w;
        }
        __syncthreads();
    }
    reinterpret_cast<float4*>(d_agg + n * H_DIM)[t] = acc;
}

// =================================================================================
// 4. main loop (launch #4 — profiled): wav + base, packed f32x2
//    RN=16, SPLIT=8, merged accumulator
//    grid (4 o-strips, 64 n-tiles, 8 i-splits) = 2048 blocks, 8KB smem, ~48 regs
// =================================================================================
__global__ void __launch_bounds__(128) k_wavbase() {
    __shared__ ulonglong2 s_pair[ISPLIT * NPAIR];     // [i_local][p] = {agg01, sa01}
    float* s_f = reinterpret_cast<float*>(s_pair);
    int t  = threadIdx.x;
    int o  = blockIdx.x * 128 + t;
    int n0 = blockIdx.y * RN;
    int i0 = blockIdx.z * ISPLIT;

    // stage agg + silu(agg) for this block's i-range, node-pair-contiguous
    for (int idx = t; idx < (ISPLIT / 4) * RN; idx += 128) {
        int c = idx / RN;                             // local i-chunk of 4
        int n = idx % RN;
        float4 a4 = *reinterpret_cast<const float4*>(&d_agg[(n0 + n) * H_DIM + i0 + c * 4]);
        int p = n >> 1, half = n & 1;
        float av[4] = {a4.x, a4.y, a4.z, a4.w};
#pragma unroll
        for (int d = 0; d < 4; d++) {
            int i = c * 4 + d;
            float a  = av[d];
            float sa = a * fsigmoid(a);
            int base = (i * NPAIR + p) * 4;
            s_f[base + half]     = a;
            s_f[base + 2 + half] = sa;
        }
    }
    __syncthreads();

    u64 acc[NPAIR];
#pragma unroll
    for (int p = 0; p < NPAIR; p++) acc[p] = 0ull;
    const u64 cc2 = pack2(NEG_HALF_LOG2E, NEG_HALF_LOG2E);

    for (int i = 0; i < ISPLIT; i++) {
        float4 w = __ldg(&d_wpack[(i0 + i) * H_DIM + o]); // {invS, -T*invS, C*Ww, Wb}
        u64 wx2 = pack2(w.x, w.x);
        u64 wy2 = pack2(w.y, w.y);
        float nz = -w.z;
        u64 nwz2 = pack2(nz, nz);
        u64 wz2  = pack2(w.z, w.z);
        u64 ww2  = pack2(w.w, w.w);
        const ulonglong2* row = &s_pair[i * NPAIR];
#pragma unroll
        for (int p = 0; p < NPAIR; p++) {
            ulonglong2 v = row[p];
            u64 u   = fma2(v.x, wx2, wy2);            // (agg - T)/S
            u64 tt  = mul2(u, u);
            u64 arg = mul2(tt, cc2);
            float alo, ahi; unpack2(arg, alo, ahi);
            u64 e   = pack2(ex2f(alo), ex2f(ahi));    // exp(-u^2/2)
            u64 g   = fma2(tt, nwz2, wz2);            // C*W*(1 - u^2)
            acc[p]  = fma2(v.y, ww2, acc[p]);         // base contribution
            acc[p]  = fma2(g, e, acc[p]);             // wavelet contribution
        }
    }
    float* part = d_partial + blockIdx.z * (N_NODES * H_DIM);
#pragma unroll
    for (int p = 0; p < NPAIR; p++) {
        float w0, w1;
        unpack2(acc[p], w0, w1);
        part[(n0 + 2 * p)     * H_DIM + o] = w0;
        part[(n0 + 2 * p + 1) * H_DIM + o] = w1;
    }
}

// =================================================================================
// 5. stats over conv columns (conv = sum of 8 partials):
//    blocks [0,15]  : colstats with triple-bn fold
//    blocks [16,47] : pool sums (atomic-free)
// =================================================================================
__device__ __forceinline__ float conv_at(int n, int col) {
    int idx = n * H_DIM + col;
    float v = 0.0f;
#pragma unroll
    for (int sp = 0; sp < SPLIT; sp++)
        v += d_partial[sp * (N_NODES * H_DIM) + idx];
    return v;
}

__global__ void __launch_bounds__(256) k_stats_conv() {
    int blk = blockIdx.x, t = threadIdx.x;
    if (blk < 16) {                                   // ---- colstats (conv) ----
        __shared__ float ssum[8][32], ssq[8][32];
        int c = t & 31, r = t >> 5;
        int col = blk * 32 + c;
        int j = F_DIM + col;
        float s = 0.0f, q = 0.0f;
        for (int n = r; n < N_NODES; n += 8) {
            float v = conv_at(n, col);
            s += v; q = fmaf(v, v, q);
        }
        ssum[r][c] = s; ssq[r][c] = q;
        __syncthreads();
        if (r == 0) {
#pragma unroll
            for (int rr = 1; rr < 8; rr++) { s += ssum[rr][c]; q += ssq[rr][c]; }
            float mu  = s * (1.0f / N_NODES);
            float var = fmaxf(q * (1.0f / N_NODES) - mu * mu, 0.0f);
            float a1 = rsqrtf(var + EPSB);
            float v1 = var / (var + EPSB);
            float a2 = rsqrtf(v1 + EPSB);
            float v2 = v1 / (v1 + EPSB);
            float a3 = rsqrtf(v2 + EPSB);
            d_mu[j] = mu;
            d_sc[j] = a1 * a2 * a3;
        }
        return;
    }
    {                                                 // ---- pool sums (conv) ----
        int w   = blk - 16;                           // 0..31
        int b   = w >> 1;
        int ch  = w & 1;
        int col = ch * 256 + t;
        int j   = F_DIM + col;
        int beg = d_roff[b], end = d_roff[b + 1];
        float s = 0.0f;
        for (int n = beg; n < end; n++) s += conv_at(n, col);
        d_gsum[b * Z_DIM + j] = s;
    }
}

// =================================================================================
// 6. fc1 + relu (128 blocks x 128 thr; 4 output-warps per block)
// =================================================================================
__global__ void __launch_bounds__(128) k_fc1(const float* __restrict__ w,
                                             const float* __restrict__ bias) {
    int warp = blockIdx.x * 4 + (threadIdx.x >> 5);   // 0..511 = o
    int lane = threadIdx.x & 31;
    float rcnt[B_GRAPHS];
#pragma unroll
    for (int b = 0; b < B_GRAPHS; b++) {
        int c = d_roff[b + 1] - d_roff[b];
        rcnt[b] = (c > 0) ? (1.0f / (float)c) : 0.0f;
    }
    float acc[B_GRAPHS];
#pragma unroll
    for (int b = 0; b < B_GRAPHS; b++) acc[b] = 0.0f;
    for (int k0 = 0; k0 < Z_DIM; k0 += 32) {
        int j = k0 + lane;
        float wv = w[warp * Z_DIM + j];
        float mu = d_mu[j], sc = d_sc[j];
#pragma unroll
        for (int b = 0; b < B_GRAPHS; b++) {
            float pooled = (d_gsum[b * Z_DIM + j] * rcnt[b] - mu) * sc;
            if (rcnt[b] == 0.0f) pooled = 0.0f;
            acc[b] = fmaf(wv, pooled, acc[b]);
        }
    }
#pragma unroll
    for (int b = 0; b < B_GRAPHS; b++) {
        float s = acc[b];
        s += __shfl_xor_sync(0xffffffffu, s, 16);
        s += __shfl_xor_sync(0xffffffffu, s, 8);
        s += __shfl_xor_sync(0xffffffffu, s, 4);
        s += __shfl_xor_sync(0xffffffffu, s, 2);
        s += __shfl_xor_sync(0xffffffffu, s, 1);
        acc[b] = s;
    }
    if (lane == 0) {
        float bi = bias[warp];
#pragma unroll
        for (int b = 0; b < B_GRAPHS; b++)
            d_h1[b * 512 + warp] = fmaxf(acc[b] + bi, 0.0f);
    }
}

// =================================================================================
// 7. fc2: one warp per (graph, output)
// =================================================================================
__global__ void __launch_bounds__(1024) k_fc2(const float* __restrict__ w,
                                              const float* __restrict__ bias,
                                              float* __restrict__ out) {
    int gw   = (blockIdx.x * blockDim.x + threadIdx.x) >> 5;  // 0..159
    int lane = threadIdx.x & 31;
    if (gw >= B_GRAPHS * OUT_DIM) return;
    int b = gw / OUT_DIM, k = gw % OUT_DIM;
    float s = 0.0f;
#pragma unroll
    for (int i = 0; i < 512 / 32; i++) {
        int o = i * 32 + lane;
        s = fmaf(d_h1[b * 512 + o], w[k * 512 + o], s);
    }
    s += __shfl_xor_sync(0xffffffffu, s, 16);
    s += __shfl_xor_sync(0xffffffffu, s, 8);
    s += __shfl_xor_sync(0xffffffffu, s, 4);
    s += __shfl_xor_sync(0xffffffffu, s, 2);
    s += __shfl_xor_sync(0xffffffffu, s, 1);
    if (lane == 0) out[b * OUT_DIM + k] = s + bias[k];
}

// ---------------- launch ----------------------------------------------------------
extern "C" void kernel_launch(void* const* d_in, const int* in_sizes, int n_in,
                              void* d_out, int out_size) {
    const float* x      = (const float*)d_in[0];
    const float* w_att  = (const float*)d_in[1];
    const float* wscale = (const float*)d_in[2];
    const float* wtrans = (const float*)d_in[3];
    const float* wwav   = (const float*)d_in[4];
    const float* wbase  = (const float*)d_in[5];
    const float* fc1w   = (const float*)d_in[6];
    const float* fc1b   = (const float*)d_in[7];
    const float* fc2w   = (const float*)d_in[8];
    const float* fc2b   = (const float*)d_in[9];
    const int*   eidx   = (const int*)d_in[10];
    const int*   batch  = (const int*)d_in[11];
    float*       out    = (float*)d_out;

    k_setup<<<770, 1024>>>(x, w_att, wscale, wtrans, wwav, wbase, eidx, batch); // #1
    k_stats_x<<<96, 256>>>(x);                                        // #2
    k_gather<<<N_NODES, 128>>>();                                     // #3
    k_wavbase<<<dim3(H_DIM / 128, N_NODES / RN, SPLIT), 128>>>();     // #4 (profiled)
    k_stats_conv<<<48, 256>>>();                                      // #5
    k_fc1<<<128, 128>>>(fc1w, fc1b);                                  // #6
    k_fc2<<<5, 1024>>>(fc2w, fc2b, out);                              // #7
}

// round 13
// speedup vs baseline: 1.1145x; 1.1145x over previous
#include <cuda_runtime.h>
#include <cstdint>

#define N_NODES 1024
#define F_DIM   1024
#define H_DIM   512
#define E_EDGES 32768
#define B_GRAPHS 16
#define OUT_DIM 10
#define Z_DIM   (F_DIM + H_DIM)   // 1536
#define EPSB    1e-5f
#define MH_Cf   0.8673250705840776f
#define NEG_HALF_LOG2E (-0.7213475204444817f)
#define LOG2E   1.4426950408889634f
#define INV_SQRT2 0.7071067811865476f
#define RN 16                      // nodes per wavbase block
#define NPAIR (RN / 2)             // 8
#define SPLIT 8                    // i-dimension split factor
#define ISPLIT (H_DIM / SPLIT)     // 64 i's per block

// ---------------- scratch (static device memory; no allocations) ----------------
__device__ __align__(16) float  d_h   [N_NODES * H_DIM];
__device__ __align__(16) float  d_agg [N_NODES * H_DIM];
__device__ __align__(16) float4 d_wpack[H_DIM * H_DIM];   // [i][o] = {invS, -T*invS, C*Wwav, Wbase}
__device__ __align__(16) float  d_conv[N_NODES * H_DIM];  // wav+base (RED-accumulated)
__device__ float d_mu [Z_DIM];
__device__ float d_sc [Z_DIM];
__device__ float d_gsum[B_GRAPHS * Z_DIM];
__device__ float d_h1 [B_GRAPHS * 512];
// CSR scratch
__device__ int d_off [N_NODES + 1];
__device__ int d_elist[E_EDGES];
__device__ int d_roff[B_GRAPHS + 1];   // per-graph node ranges (batch is sorted)

__device__ __forceinline__ float ex2f(float x) {
    float r; asm("ex2.approx.ftz.f32 %0, %1;" : "=f"(r) : "f"(x)); return r;
}
__device__ __forceinline__ float fsigmoid(float t) {
    return 1.0f / (1.0f + ex2f(-t * LOG2E));
}

// ---- f32x2 packed-math helpers (sm_103a) ----
typedef unsigned long long u64;
__device__ __forceinline__ u64 pack2(float lo, float hi) {
    u64 r; asm("mov.b64 %0, {%1, %2};" : "=l"(r) : "f"(lo), "f"(hi)); return r;
}
__device__ __forceinline__ void unpack2(u64 v, float& lo, float& hi) {
    asm("mov.b64 {%0, %1}, %2;" : "=f"(lo), "=f"(hi) : "l"(v));
}
__device__ __forceinline__ u64 fma2(u64 a, u64 b, u64 c) {
    u64 d; asm("fma.rn.f32x2 %0, %1, %2, %3;" : "=l"(d) : "l"(a), "l"(b), "l"(c)); return d;
}
__device__ __forceinline__ u64 mul2(u64 a, u64 b) {
    u64 d; asm("mul.rn.f32x2 %0, %1, %2;" : "=l"(d) : "l"(a), "l"(b)); return d;
}

// =================================================================================
// 1. setup (1024-thread blocks):
//    blocks [0,255]   : wpack
//    blocks [256,767] : h
//    block  768       : CSR build (deg -> warp-shuffle scan -> fill)
//    block  769       : graph ranges
//    blocks [770,897] : zero d_conv (float4)
// =================================================================================
__global__ void __launch_bounds__(1024) k_setup(
        const float* __restrict__ x,      const float* __restrict__ watt,
        const float* __restrict__ scale,  const float* __restrict__ trans,
        const float* __restrict__ wavw,   const float* __restrict__ basew,
        const int*   __restrict__ ei,     const int*   __restrict__ batch) {
    int blk = blockIdx.x, t = threadIdx.x;

    if (blk < 256) {                                // ---- wpack ----
        int idx = blk * 1024 + t;                   // idx = o*512 + i
        int o = idx >> 9, i = idx & 511;
        float invS = 1.0f / scale[idx];
        d_wpack[i * H_DIM + o] = make_float4(invS, -trans[idx] * invS,
                                             MH_Cf * wavw[idx], basew[idx]);
        return;
    }
    if (blk < 768) {                                // ---- h ----
        int idx = (blk - 256) * 1024 + t;           // n*H + j
        int n = idx >> 9, j = idx & 511;
        float2 p = reinterpret_cast<const float2*>(x)[n * (F_DIM / 2) + j];
        float lo = (p.x + p.y) * INV_SQRT2;
        float hi = (p.x - p.y) * INV_SQRT2;
        float s  = fsigmoid(lo * watt[0] + hi * watt[1]);
        d_h[idx] = hi + s * (lo - hi);
        return;
    }
    if (blk == 768) {                               // ---- CSR build ----
        __shared__ int s[N_NODES];
        __shared__ int wsum[32];
        s[t] = 0;
        __syncthreads();
        for (int e = t; e < E_EDGES; e += 1024)
            atomicAdd(&s[ei[E_EDGES + e]], 1);
        __syncthreads();
        int v = s[t];
        int lane = t & 31, wid = t >> 5;
        int inc = v;
#pragma unroll
        for (int d = 1; d < 32; d <<= 1) {
            int up = __shfl_up_sync(0xffffffffu, inc, d);
            if (lane >= d) inc += up;
        }
        if (lane == 31) wsum[wid] = inc;
        __syncthreads();
        if (wid == 0) {
            int wv = wsum[lane];
            int winc = wv;
#pragma unroll
            for (int d = 1; d < 32; d <<= 1) {
                int up = __shfl_up_sync(0xffffffffu, winc, d);
                if (lane >= d) winc += up;
            }
            wsum[lane] = winc - wv;                 // exclusive warp offsets
        }
        __syncthreads();
        int excl = wsum[wid] + inc - v;
        d_off[t] = excl;
        if (t == N_NODES - 1) d_off[N_NODES] = excl + v;
        __syncthreads();
        s[t] = excl;                                // fill cursors
        __syncthreads();
        for (int e = t; e < E_EDGES; e += 1024) {
            int dst = ei[E_EDGES + e];
            int pos = atomicAdd(&s[dst], 1);
            d_elist[pos] = ei[e];
        }
        return;
    }
    if (blk == 769) {                               // ---- graph ranges ----
        __shared__ int rs[B_GRAPHS + 1];
        if (t <= B_GRAPHS) rs[t] = -1;
        __syncthreads();
        for (int n = t; n < N_NODES; n += 1024) {
            int b = batch[n];
            if (n == 0 || batch[n - 1] != b) rs[b] = n;
        }
        __syncthreads();
        if (t == 0) {
            rs[B_GRAPHS] = N_NODES;
            for (int b = B_GRAPHS - 1; b >= 0; b--)
                if (rs[b] < 0) rs[b] = rs[b + 1];
            for (int b = 0; b <= B_GRAPHS; b++) d_roff[b] = rs[b];
        }
        return;
    }
    {                                               // ---- zero d_conv ----
        int idx = (blk - 770) * 1024 + t;           // float4 index
        reinterpret_cast<float4*>(d_conv)[idx] = make_float4(0.f, 0.f, 0.f, 0.f);
    }
}

// =================================================================================
// 2. stats over x columns:
//    blocks [0,31]  : colstats -> d_mu, d_sc for j in [0,1024)
//    blocks [32,95] : pool sums (16 graphs x 4 chunks, atomic-free)
// =================================================================================
__global__ void __launch_bounds__(256) k_stats_x(const float* __restrict__ x) {
    int blk = blockIdx.x, t = threadIdx.x;
    if (blk < 32) {                                   // ---- colstats (x) ----
        __shared__ float ssum[8][32], ssq[8][32];
        int c = t & 31, r = t >> 5;
        int j = blk * 32 + c;
        float s = 0.0f, q = 0.0f;
        for (int n = r; n < N_NODES; n += 8) {
            float v = x[n * F_DIM + j];
            s += v; q = fmaf(v, v, q);
        }
        ssum[r][c] = s; ssq[r][c] = q;
        __syncthreads();
        if (r == 0) {
#pragma unroll
            for (int rr = 1; rr < 8; rr++) { s += ssum[rr][c]; q += ssq[rr][c]; }
            float mu  = s * (1.0f / N_NODES);
            float var = fmaxf(q * (1.0f / N_NODES) - mu * mu, 0.0f);
            d_mu[j] = mu;
            d_sc[j] = rsqrtf(var + EPSB);
        }
        return;
    }
    {                                                 // ---- pool sums (x) ----
        int w   = blk - 32;                           // 0..63
        int b   = w >> 2;
        int ch  = w & 3;
        int j   = ch * 256 + t;
        int beg = d_roff[b], end = d_roff[b + 1];
        float s = 0.0f;
        int n = beg;
        for (; n + 4 <= end; n += 4) {
            float v0 = x[n * F_DIM + j];
            float v1 = x[(n + 1) * F_DIM + j];
            float v2 = x[(n + 2) * F_DIM + j];
            float v3 = x[(n + 3) * F_DIM + j];
            s += (v0 + v1) + (v2 + v3);
        }
        for (; n < end; n++) s += x[n * F_DIM + j];
        d_gsum[b * Z_DIM + j] = s;
    }
}

// =================================================================================
// 3. gather: agg[n] = h[n] + sum_{e: dst=n} h[src]
// =================================================================================
__global__ void __launch_bounds__(128) k_gather() {
    __shared__ int se[128];
    int n = blockIdx.x, t = threadIdx.x;
    int beg = d_off[n], end = d_off[n + 1];
    float4 acc = reinterpret_cast<const float4*>(d_h + n * H_DIM)[t];
    for (int t0 = beg; t0 < end; t0 += 128) {
        int cnt = min(128, end - t0);
        if (t < cnt) se[t] = d_elist[t0 + t];
        __syncthreads();
        int k = 0;
        for (; k + 4 <= cnt; k += 4) {
            float4 v0 = reinterpret_cast<const float4*>(d_h + se[k]     * H_DIM)[t];
            float4 v1 = reinterpret_cast<const float4*>(d_h + se[k + 1] * H_DIM)[t];
            float4 v2 = reinterpret_cast<const float4*>(d_h + se[k + 2] * H_DIM)[t];
            float4 v3 = reinterpret_cast<const float4*>(d_h + se[k + 3] * H_DIM)[t];
            acc.x += v0.x + v1.x + v2.x + v3.x;
            acc.y += v0.y + v1.y + v2.y + v3.y;
            acc.z += v0.z + v1.z + v2.z + v3.z;
            acc.w += v0.w + v1.w + v2.w + v3.w;
        }
        for (; k < cnt; k++) {
            float4 v = reinterpret_cast<const float4*>(d_h + se[k] * H_DIM)[t];
            acc.x += v.x; acc.y += v.y; acc.z += v.z; acc.w += v.w;
        }
        __syncthreads();
    }
    reinterpret_cast<float4*>(d_agg + n * H_DIM)[t] = acc;
}

// =================================================================================
// 4. main loop (launch #4 — profiled): wav + base, packed f32x2
//    RN=16, SPLIT=8, merged accumulator; output via RED into d_conv
//    grid (4 o-strips, 64 n-tiles, 8 i-splits) = 2048 blocks, 8KB smem, ~48 regs
// =================================================================================
__global__ void __launch_bounds__(128) k_wavbase() {
    __shared__ ulonglong2 s_pair[ISPLIT * NPAIR];     // [i_local][p] = {agg01, sa01}
    float* s_f = reinterpret_cast<float*>(s_pair);
    int t  = threadIdx.x;
    int o  = blockIdx.x * 128 + t;
    int n0 = blockIdx.y * RN;
    int i0 = blockIdx.z * ISPLIT;

    // stage agg + silu(agg) for this block's i-range, node-pair-contiguous
    for (int idx = t; idx < (ISPLIT / 4) * RN; idx += 128) {
        int c = idx / RN;                             // local i-chunk of 4
        int n = idx % RN;
        float4 a4 = *reinterpret_cast<const float4*>(&d_agg[(n0 + n) * H_DIM + i0 + c * 4]);
        int p = n >> 1, half = n & 1;
        float av[4] = {a4.x, a4.y, a4.z, a4.w};
#pragma unroll
        for (int d = 0; d < 4; d++) {
            int i = c * 4 + d;
            float a  = av[d];
            float sa = a * fsigmoid(a);
            int base = (i * NPAIR + p) * 4;
            s_f[base + half]     = a;
            s_f[base + 2 + half] = sa;
        }
    }
    __syncthreads();

    u64 acc[NPAIR];
#pragma unroll
    for (int p = 0; p < NPAIR; p++) acc[p] = 0ull;
    const u64 cc2 = pack2(NEG_HALF_LOG2E, NEG_HALF_LOG2E);

    for (int i = 0; i < ISPLIT; i++) {
        float4 w = __ldg(&d_wpack[(i0 + i) * H_DIM + o]); // {invS, -T*invS, C*Ww, Wb}
        u64 wx2 = pack2(w.x, w.x);
        u64 wy2 = pack2(w.y, w.y);
        float nz = -w.z;
        u64 nwz2 = pack2(nz, nz);
        u64 wz2  = pack2(w.z, w.z);
        u64 ww2  = pack2(w.w, w.w);
        const ulonglong2* row = &s_pair[i * NPAIR];
#pragma unroll
        for (int p = 0; p < NPAIR; p++) {
            ulonglong2 v = row[p];
            u64 u   = fma2(v.x, wx2, wy2);            // (agg - T)/S
            u64 tt  = mul2(u, u);
            u64 arg = mul2(tt, cc2);
            float alo, ahi; unpack2(arg, alo, ahi);
            u64 e   = pack2(ex2f(alo), ex2f(ahi));    // exp(-u^2/2)
            u64 g   = fma2(tt, nwz2, wz2);            // C*W*(1 - u^2)
            acc[p]  = fma2(v.y, ww2, acc[p]);         // base contribution
            acc[p]  = fma2(g, e, acc[p]);             // wavelet contribution
        }
    }
#pragma unroll
    for (int p = 0; p < NPAIR; p++) {
        float w0, w1;
        unpack2(acc[p], w0, w1);
        atomicAdd(&d_conv[(n0 + 2 * p)     * H_DIM + o], w0);   // RED (no return)
        atomicAdd(&d_conv[(n0 + 2 * p + 1) * H_DIM + o], w1);
    }
}

// =================================================================================
// 5. stats over conv columns (reads d_conv directly):
//    blocks [0,15]  : colstats with triple-bn fold
//    blocks [16,47] : pool sums (atomic-free)
// =================================================================================
__global__ void __launch_bounds__(256) k_stats_conv() {
    int blk = blockIdx.x, t = threadIdx.x;
    if (blk < 16) {                                   // ---- colstats (conv) ----
        __shared__ float ssum[8][32], ssq[8][32];
        int c = t & 31, r = t >> 5;
        int col = blk * 32 + c;
        int j = F_DIM + col;
        float s = 0.0f, q = 0.0f;
        for (int n = r; n < N_NODES; n += 8) {
            float v = d_conv[n * H_DIM + col];
            s += v; q = fmaf(v, v, q);
        }
        ssum[r][c] = s; ssq[r][c] = q;
        __syncthreads();
        if (r == 0) {
#pragma unroll
            for (int rr = 1; rr < 8; rr++) { s += ssum[rr][c]; q += ssq[rr][c]; }
            float mu  = s * (1.0f / N_NODES);
            float var = fmaxf(q * (1.0f / N_NODES) - mu * mu, 0.0f);
            float a1 = rsqrtf(var + EPSB);
            float v1 = var / (var + EPSB);
            float a2 = rsqrtf(v1 + EPSB);
            float v2 = v1 / (v1 + EPSB);
            float a3 = rsqrtf(v2 + EPSB);
            d_mu[j] = mu;
            d_sc[j] = a1 * a2 * a3;
        }
        return;
    }
    {                                                 // ---- pool sums (conv) ----
        int w   = blk - 16;                           // 0..31
        int b   = w >> 1;
        int ch  = w & 1;
        int col = ch * 256 + t;
        int j   = F_DIM + col;
        int beg = d_roff[b], end = d_roff[b + 1];
        float s = 0.0f;
        int n = beg;
        for (; n + 4 <= end; n += 4) {
            float v0 = d_conv[n * H_DIM + col];
            float v1 = d_conv[(n + 1) * H_DIM + col];
            float v2 = d_conv[(n + 2) * H_DIM + col];
            float v3 = d_conv[(n + 3) * H_DIM + col];
            s += (v0 + v1) + (v2 + v3);
        }
        for (; n < end; n++) s += d_conv[n * H_DIM + col];
        d_gsum[b * Z_DIM + j] = s;
    }
}

// =================================================================================
// 6. fc1 + relu (R11 config: 16 blocks x 1024 thr)
// =================================================================================
__global__ void __launch_bounds__(1024) k_fc1(const float* __restrict__ w,
                                              const float* __restrict__ bias) {
    int warp = (blockIdx.x * blockDim.x + threadIdx.x) >> 5;  // 0..511 = o
    int lane = threadIdx.x & 31;
    float rcnt[B_GRAPHS];
#pragma unroll
    for (int b = 0; b < B_GRAPHS; b++) {
        int c = d_roff[b + 1] - d_roff[b];
        rcnt[b] = (c > 0) ? (1.0f / (float)c) : 0.0f;
    }
    float acc[B_GRAPHS];
#pragma unroll
    for (int b = 0; b < B_GRAPHS; b++) acc[b] = 0.0f;
    for (int k0 = 0; k0 < Z_DIM; k0 += 32) {
        int j = k0 + lane;
        float wv = w[warp * Z_DIM + j];
        float mu = d_mu[j], sc = d_sc[j];
#pragma unroll
        for (int b = 0; b < B_GRAPHS; b++) {
            float pooled = (d_gsum[b * Z_DIM + j] * rcnt[b] - mu) * sc;
            if (rcnt[b] == 0.0f) pooled = 0.0f;
            acc[b] = fmaf(wv, pooled, acc[b]);
        }
    }
#pragma unroll
    for (int b = 0; b < B_GRAPHS; b++) {
        float s = acc[b];
        s += __shfl_xor_sync(0xffffffffu, s, 16);
        s += __shfl_xor_sync(0xffffffffu, s, 8);
        s += __shfl_xor_sync(0xffffffffu, s, 4);
        s += __shfl_xor_sync(0xffffffffu, s, 2);
        s += __shfl_xor_sync(0xffffffffu, s, 1);
        acc[b] = s;
    }
    if (lane == 0) {
        float bi = bias[warp];
#pragma unroll
        for (int b = 0; b < B_GRAPHS; b++)
            d_h1[b * 512 + warp] = fmaxf(acc[b] + bi, 0.0f);
    }
}

// =================================================================================
// 7. fc2: one warp per (graph, output)
// =================================================================================
__global__ void __launch_bounds__(1024) k_fc2(const float* __restrict__ w,
                                              const float* __restrict__ bias,
                                              float* __restrict__ out) {
    int gw   = (blockIdx.x * blockDim.x + threadIdx.x) >> 5;  // 0..159
    int lane = threadIdx.x & 31;
    if (gw >= B_GRAPHS * OUT_DIM) return;
    int b = gw / OUT_DIM, k = gw % OUT_DIM;
    float s = 0.0f;
#pragma unroll
    for (int i = 0; i < 512 / 32; i++) {
        int o = i * 32 + lane;
        s = fmaf(d_h1[b * 512 + o], w[k * 512 + o], s);
    }
    s += __shfl_xor_sync(0xffffffffu, s, 16);
    s += __shfl_xor_sync(0xffffffffu, s, 8);
    s += __shfl_xor_sync(0xffffffffu, s, 4);
    s += __shfl_xor_sync(0xffffffffu, s, 2);
    s += __shfl_xor_sync(0xffffffffu, s, 1);
    if (lane == 0) out[b * OUT_DIM + k] = s + bias[k];
}

// ---------------- launch ----------------------------------------------------------
extern "C" void kernel_launch(void* const* d_in, const int* in_sizes, int n_in,
                              void* d_out, int out_size) {
    const float* x      = (const float*)d_in[0];
    const float* w_att  = (const float*)d_in[1];
    const float* wscale = (const float*)d_in[2];
    const float* wtrans = (const float*)d_in[3];
    const float* wwav   = (const float*)d_in[4];
    const float* wbase  = (const float*)d_in[5];
    const float* fc1w   = (const float*)d_in[6];
    const float* fc1b   = (const float*)d_in[7];
    const float* fc2w   = (const float*)d_in[8];
    const float* fc2b   = (const float*)d_in[9];
    const int*   eidx   = (const int*)d_in[10];
    const int*   batch  = (const int*)d_in[11];
    float*       out    = (float*)d_out;

    k_setup<<<898, 1024>>>(x, w_att, wscale, wtrans, wwav, wbase, eidx, batch); // #1
    k_stats_x<<<96, 256>>>(x);                                        // #2
    k_gather<<<N_NODES, 128>>>();                                     // #3
    k_wavbase<<<dim3(H_DIM / 128, N_NODES / RN, SPLIT), 128>>>();     // #4 (profiled)
    k_stats_conv<<<48, 256>>>();                                      // #5
    k_fc1<<<16, 1024>>>(fc1w, fc1b);                                  // #6
    k_fc2<<<5, 1024>>>(fc2w, fc2b, out);                              // #7
}

// round 14
// speedup vs baseline: 1.4479x; 1.2991x over previous
#include <cuda_runtime.h>
#include <cstdint>

#define N_NODES 1024
#define F_DIM   1024
#define H_DIM   512
#define E_EDGES 32768
#define B_GRAPHS 16
#define OUT_DIM 10
#define Z_DIM   (F_DIM + H_DIM)   // 1536
#define EPSB    1e-5f
#define MH_Cf   0.8673250705840776f
#define NEG_HALF_LOG2E (-0.7213475204444817f)
#define LOG2E   1.4426950408889634f
#define INV_SQRT2 0.7071067811865476f
#define RN 16                      // nodes per wavbase block
#define NPAIR (RN / 2)             // 8
#define SPLIT 8                    // i-dimension split factor
#define ISPLIT (H_DIM / SPLIT)     // 64 i's per block

// ---------------- scratch (static device memory; no allocations) ----------------
__device__ __align__(16) float  d_h   [N_NODES * H_DIM];
__device__ __align__(16) float  d_agg [N_NODES * H_DIM];
__device__ __align__(16) float4 d_wpack[H_DIM * H_DIM];   // [i][o] = {invS, -T*invS, C*Wwav, Wbase}
__device__ __align__(16) float  d_conv[N_NODES * H_DIM];  // wav+base (RED-accumulated)
__device__ float d_mu [Z_DIM];
__device__ float d_sc [Z_DIM];
__device__ float d_gsum[B_GRAPHS * Z_DIM];
__device__ __align__(16) float d_pooled_t[Z_DIM * B_GRAPHS];  // [j][b] transposed pooled
__device__ float d_h1 [B_GRAPHS * 512];
// CSR scratch
__device__ int d_off [N_NODES + 1];
__device__ int d_elist[E_EDGES];
__device__ int d_roff[B_GRAPHS + 1];   // per-graph node ranges (batch is sorted)

__device__ __forceinline__ float ex2f(float x) {
    float r; asm("ex2.approx.ftz.f32 %0, %1;" : "=f"(r) : "f"(x)); return r;
}
__device__ __forceinline__ float fsigmoid(float t) {
    return 1.0f / (1.0f + ex2f(-t * LOG2E));
}

// ---- f32x2 packed-math helpers (sm_103a) ----
typedef unsigned long long u64;
__device__ __forceinline__ u64 pack2(float lo, float hi) {
    u64 r; asm("mov.b64 %0, {%1, %2};" : "=l"(r) : "f"(lo), "f"(hi)); return r;
}
__device__ __forceinline__ void unpack2(u64 v, float& lo, float& hi) {
    asm("mov.b64 {%0, %1}, %2;" : "=f"(lo), "=f"(hi) : "l"(v));
}
__device__ __forceinline__ u64 fma2(u64 a, u64 b, u64 c) {
    u64 d; asm("fma.rn.f32x2 %0, %1, %2, %3;" : "=l"(d) : "l"(a), "l"(b), "l"(c)); return d;
}
__device__ __forceinline__ u64 mul2(u64 a, u64 b) {
    u64 d; asm("mul.rn.f32x2 %0, %1, %2;" : "=l"(d) : "l"(a), "l"(b)); return d;
}

// =================================================================================
// 1. setup (1024-thread blocks):
//    blocks [0,255]   : wpack
//    blocks [256,767] : h
//    block  768       : CSR build (deg -> warp-shuffle scan -> fill)
//    block  769       : graph ranges
//    blocks [770,897] : zero d_conv (float4)
// =================================================================================
__global__ void __launch_bounds__(1024) k_setup(
        const float* __restrict__ x,      const float* __restrict__ watt,
        const float* __restrict__ scale,  const float* __restrict__ trans,
        const float* __restrict__ wavw,   const float* __restrict__ basew,
        const int*   __restrict__ ei,     const int*   __restrict__ batch) {
    int blk = blockIdx.x, t = threadIdx.x;

    if (blk < 256) {                                // ---- wpack ----
        int idx = blk * 1024 + t;                   // idx = o*512 + i
        int o = idx >> 9, i = idx & 511;
        float invS = 1.0f / scale[idx];
        d_wpack[i * H_DIM + o] = make_float4(invS, -trans[idx] * invS,
                                             MH_Cf * wavw[idx], basew[idx]);
        return;
    }
    if (blk < 768) {                                // ---- h ----
        int idx = (blk - 256) * 1024 + t;           // n*H + j
        int n = idx >> 9, j = idx & 511;
        float2 p = reinterpret_cast<const float2*>(x)[n * (F_DIM / 2) + j];
        float lo = (p.x + p.y) * INV_SQRT2;
        float hi = (p.x - p.y) * INV_SQRT2;
        float s  = fsigmoid(lo * watt[0] + hi * watt[1]);
        d_h[idx] = hi + s * (lo - hi);
        return;
    }
    if (blk == 768) {                               // ---- CSR build ----
        __shared__ int s[N_NODES];
        __shared__ int wsum[32];
        s[t] = 0;
        __syncthreads();
        for (int e = t; e < E_EDGES; e += 1024)
            atomicAdd(&s[ei[E_EDGES + e]], 1);
        __syncthreads();
        int v = s[t];
        int lane = t & 31, wid = t >> 5;
        int inc = v;
#pragma unroll
        for (int d = 1; d < 32; d <<= 1) {
            int up = __shfl_up_sync(0xffffffffu, inc, d);
            if (lane >= d) inc += up;
        }
        if (lane == 31) wsum[wid] = inc;
        __syncthreads();
        if (wid == 0) {
            int wv = wsum[lane];
            int winc = wv;
#pragma unroll
            for (int d = 1; d < 32; d <<= 1) {
                int up = __shfl_up_sync(0xffffffffu, winc, d);
                if (lane >= d) winc += up;
            }
            wsum[lane] = winc - wv;                 // exclusive warp offsets
        }
        __syncthreads();
        int excl = wsum[wid] + inc - v;
        d_off[t] = excl;
        if (t == N_NODES - 1) d_off[N_NODES] = excl + v;
        __syncthreads();
        s[t] = excl;                                // fill cursors
        __syncthreads();
        for (int e = t; e < E_EDGES; e += 1024) {
            int dst = ei[E_EDGES + e];
            int pos = atomicAdd(&s[dst], 1);
            d_elist[pos] = ei[e];
        }
        return;
    }
    if (blk == 769) {                               // ---- graph ranges ----
        __shared__ int rs[B_GRAPHS + 1];
        if (t <= B_GRAPHS) rs[t] = -1;
        __syncthreads();
        for (int n = t; n < N_NODES; n += 1024) {
            int b = batch[n];
            if (n == 0 || batch[n - 1] != b) rs[b] = n;
        }
        __syncthreads();
        if (t == 0) {
            rs[B_GRAPHS] = N_NODES;
            for (int b = B_GRAPHS - 1; b >= 0; b--)
                if (rs[b] < 0) rs[b] = rs[b + 1];
            for (int b = 0; b <= B_GRAPHS; b++) d_roff[b] = rs[b];
        }
        return;
    }
    {                                               // ---- zero d_conv ----
        int idx = (blk - 770) * 1024 + t;           // float4 index
        reinterpret_cast<float4*>(d_conv)[idx] = make_float4(0.f, 0.f, 0.f, 0.f);
    }
}

// =================================================================================
// 2. stats over x columns:
//    blocks [0,31]  : colstats -> d_mu, d_sc for j in [0,1024)
//    blocks [32,95] : pool sums (16 graphs x 4 chunks, atomic-free)
// =================================================================================
__global__ void __launch_bounds__(256) k_stats_x(const float* __restrict__ x) {
    int blk = blockIdx.x, t = threadIdx.x;
    if (blk < 32) {                                   // ---- colstats (x) ----
        __shared__ float ssum[8][32], ssq[8][32];
        int c = t & 31, r = t >> 5;
        int j = blk * 32 + c;
        float s = 0.0f, q = 0.0f;
        for (int n = r; n < N_NODES; n += 8) {
            float v = x[n * F_DIM + j];
            s += v; q = fmaf(v, v, q);
        }
        ssum[r][c] = s; ssq[r][c] = q;
        __syncthreads();
        if (r == 0) {
#pragma unroll
            for (int rr = 1; rr < 8; rr++) { s += ssum[rr][c]; q += ssq[rr][c]; }
            float mu  = s * (1.0f / N_NODES);
            float var = fmaxf(q * (1.0f / N_NODES) - mu * mu, 0.0f);
            d_mu[j] = mu;
            d_sc[j] = rsqrtf(var + EPSB);
        }
        return;
    }
    {                                                 // ---- pool sums (x) ----
        int w   = blk - 32;                           // 0..63
        int b   = w >> 2;
        int ch  = w & 3;
        int j   = ch * 256 + t;
        int beg = d_roff[b], end = d_roff[b + 1];
        float s = 0.0f;
        int n = beg;
        for (; n + 4 <= end; n += 4) {
            float v0 = x[n * F_DIM + j];
            float v1 = x[(n + 1) * F_DIM + j];
            float v2 = x[(n + 2) * F_DIM + j];
            float v3 = x[(n + 3) * F_DIM + j];
            s += (v0 + v1) + (v2 + v3);
        }
        for (; n < end; n++) s += x[n * F_DIM + j];
        d_gsum[b * Z_DIM + j] = s;
    }
}

// =================================================================================
// 3. gather: agg[n] = h[n] + sum_{e: dst=n} h[src]
// =================================================================================
__global__ void __launch_bounds__(128) k_gather() {
    __shared__ int se[128];
    int n = blockIdx.x, t = threadIdx.x;
    int beg = d_off[n], end = d_off[n + 1];
    float4 acc = reinterpret_cast<const float4*>(d_h + n * H_DIM)[t];
    for (int t0 = beg; t0 < end; t0 += 128) {
        int cnt = min(128, end - t0);
        if (t < cnt) se[t] = d_elist[t0 + t];
        __syncthreads();
        int k = 0;
        for (; k + 4 <= cnt; k += 4) {
            float4 v0 = reinterpret_cast<const float4*>(d_h + se[k]     * H_DIM)[t];
            float4 v1 = reinterpret_cast<const float4*>(d_h + se[k + 1] * H_DIM)[t];
            float4 v2 = reinterpret_cast<const float4*>(d_h + se[k + 2] * H_DIM)[t];
            float4 v3 = reinterpret_cast<const float4*>(d_h + se[k + 3] * H_DIM)[t];
            acc.x += v0.x + v1.x + v2.x + v3.x;
            acc.y += v0.y + v1.y + v2.y + v3.y;
            acc.z += v0.z + v1.z + v2.z + v3.z;
            acc.w += v0.w + v1.w + v2.w + v3.w;
        }
        for (; k < cnt; k++) {
            float4 v = reinterpret_cast<const float4*>(d_h + se[k] * H_DIM)[t];
            acc.x += v.x; acc.y += v.y; acc.z += v.z; acc.w += v.w;
        }
        __syncthreads();
    }
    reinterpret_cast<float4*>(d_agg + n * H_DIM)[t] = acc;
}

// =================================================================================
// 4. main loop (launch #4 — profiled): wav + base, packed f32x2
//    RN=16, SPLIT=8, merged accumulator; output via RED into d_conv
// =================================================================================
__global__ void __launch_bounds__(128) k_wavbase() {
    __shared__ ulonglong2 s_pair[ISPLIT * NPAIR];     // [i_local][p] = {agg01, sa01}
    float* s_f = reinterpret_cast<float*>(s_pair);
    int t  = threadIdx.x;
    int o  = blockIdx.x * 128 + t;
    int n0 = blockIdx.y * RN;
    int i0 = blockIdx.z * ISPLIT;

    for (int idx = t; idx < (ISPLIT / 4) * RN; idx += 128) {
        int c = idx / RN;
        int n = idx % RN;
        float4 a4 = *reinterpret_cast<const float4*>(&d_agg[(n0 + n) * H_DIM + i0 + c * 4]);
        int p = n >> 1, half = n & 1;
        float av[4] = {a4.x, a4.y, a4.z, a4.w};
#pragma unroll
        for (int d = 0; d < 4; d++) {
            int i = c * 4 + d;
            float a  = av[d];
            float sa = a * fsigmoid(a);
            int base = (i * NPAIR + p) * 4;
            s_f[base + half]     = a;
            s_f[base + 2 + half] = sa;
        }
    }
    __syncthreads();

    u64 acc[NPAIR];
#pragma unroll
    for (int p = 0; p < NPAIR; p++) acc[p] = 0ull;
    const u64 cc2 = pack2(NEG_HALF_LOG2E, NEG_HALF_LOG2E);

    for (int i = 0; i < ISPLIT; i++) {
        float4 w = __ldg(&d_wpack[(i0 + i) * H_DIM + o]); // {invS, -T*invS, C*Ww, Wb}
        u64 wx2 = pack2(w.x, w.x);
        u64 wy2 = pack2(w.y, w.y);
        float nz = -w.z;
        u64 nwz2 = pack2(nz, nz);
        u64 wz2  = pack2(w.z, w.z);
        u64 ww2  = pack2(w.w, w.w);
        const ulonglong2* row = &s_pair[i * NPAIR];
#pragma unroll
        for (int p = 0; p < NPAIR; p++) {
            ulonglong2 v = row[p];
            u64 u   = fma2(v.x, wx2, wy2);
            u64 tt  = mul2(u, u);
            u64 arg = mul2(tt, cc2);
            float alo, ahi; unpack2(arg, alo, ahi);
            u64 e   = pack2(ex2f(alo), ex2f(ahi));
            u64 g   = fma2(tt, nwz2, wz2);
            acc[p]  = fma2(v.y, ww2, acc[p]);
            acc[p]  = fma2(g, e, acc[p]);
        }
    }
#pragma unroll
    for (int p = 0; p < NPAIR; p++) {
        float w0, w1;
        unpack2(acc[p], w0, w1);
        atomicAdd(&d_conv[(n0 + 2 * p)     * H_DIM + o], w0);
        atomicAdd(&d_conv[(n0 + 2 * p + 1) * H_DIM + o], w1);
    }
}

// =================================================================================
// 5. stats over conv columns:
//    blocks [0,15]  : colstats with triple-bn fold
//    blocks [16,47] : pool sums (atomic-free)
// =================================================================================
__global__ void __launch_bounds__(256) k_stats_conv() {
    int blk = blockIdx.x, t = threadIdx.x;
    if (blk < 16) {
        __shared__ float ssum[8][32], ssq[8][32];
        int c = t & 31, r = t >> 5;
        int col = blk * 32 + c;
        int j = F_DIM + col;
        float s = 0.0f, q = 0.0f;
        for (int n = r; n < N_NODES; n += 8) {
            float v = d_conv[n * H_DIM + col];
            s += v; q = fmaf(v, v, q);
        }
        ssum[r][c] = s; ssq[r][c] = q;
        __syncthreads();
        if (r == 0) {
#pragma unroll
            for (int rr = 1; rr < 8; rr++) { s += ssum[rr][c]; q += ssq[rr][c]; }
            float mu  = s * (1.0f / N_NODES);
            float var = fmaxf(q * (1.0f / N_NODES) - mu * mu, 0.0f);
            float a1 = rsqrtf(var + EPSB);
            float v1 = var / (var + EPSB);
            float a2 = rsqrtf(v1 + EPSB);
            float v2 = v1 / (v1 + EPSB);
            float a3 = rsqrtf(v2 + EPSB);
            d_mu[j] = mu;
            d_sc[j] = a1 * a2 * a3;
        }
        return;
    }
    {
        int w   = blk - 16;
        int b   = w >> 1;
        int ch  = w & 1;
        int col = ch * 256 + t;
        int j   = F_DIM + col;
        int beg = d_roff[b], end = d_roff[b + 1];
        float s = 0.0f;
        int n = beg;
        for (; n + 4 <= end; n += 4) {
            float v0 = d_conv[n * H_DIM + col];
            float v1 = d_conv[(n + 1) * H_DIM + col];
            float v2 = d_conv[(n + 2) * H_DIM + col];
            float v3 = d_conv[(n + 3) * H_DIM + col];
            s += (v0 + v1) + (v2 + v3);
        }
        for (; n < end; n++) s += d_conv[n * H_DIM + col];
        d_gsum[b * Z_DIM + j] = s;
    }
}

// =================================================================================
// 6. poolfinal: pooled_t[j][b] = (gsum[b][j]/cnt_b - mu_j) * sc_j  (transposed)
// =================================================================================
__global__ void __launch_bounds__(1024) k_poolfinal() {
    int idx = blockIdx.x * 1024 + threadIdx.x;        // j*16 + b
    if (idx >= Z_DIM * B_GRAPHS) return;
    int j = idx >> 4, b = idx & 15;
    int c = d_roff[b + 1] - d_roff[b];
    float pooled = 0.0f;
    if (c > 0)
        pooled = (d_gsum[b * Z_DIM + j] / (float)c - d_mu[j]) * d_sc[j];
    d_pooled_t[idx] = pooled;
}

// =================================================================================
// 7. fc1 + relu: 64 blocks x 256 thr, warp-per-output, vectorized pooled_t loads
// =================================================================================
__global__ void __launch_bounds__(256) k_fc1(const float* __restrict__ w,
                                             const float* __restrict__ bias) {
    int warp = blockIdx.x * 8 + (threadIdx.x >> 5);   // 0..511 = o
    int lane = threadIdx.x & 31;
    float acc[B_GRAPHS];
#pragma unroll
    for (int b = 0; b < B_GRAPHS; b++) acc[b] = 0.0f;
    for (int k0 = 0; k0 < Z_DIM; k0 += 32) {
        int j = k0 + lane;
        float wv = w[warp * Z_DIM + j];
        const float4* pt = reinterpret_cast<const float4*>(&d_pooled_t[j * B_GRAPHS]);
#pragma unroll
        for (int qq = 0; qq < 4; qq++) {
            float4 p4 = pt[qq];
            acc[qq * 4 + 0] = fmaf(wv, p4.x, acc[qq * 4 + 0]);
            acc[qq * 4 + 1] = fmaf(wv, p4.y, acc[qq * 4 + 1]);
            acc[qq * 4 + 2] = fmaf(wv, p4.z, acc[qq * 4 + 2]);
            acc[qq * 4 + 3] = fmaf(wv, p4.w, acc[qq * 4 + 3]);
        }
    }
#pragma unroll
    for (int b = 0; b < B_GRAPHS; b++) {
        float s = acc[b];
        s += __shfl_xor_sync(0xffffffffu, s, 16);
        s += __shfl_xor_sync(0xffffffffu, s, 8);
        s += __shfl_xor_sync(0xffffffffu, s, 4);
        s += __shfl_xor_sync(0xffffffffu, s, 2);
        s += __shfl_xor_sync(0xffffffffu, s, 1);
        acc[b] = s;
    }
    if (lane == 0) {
        float bi = bias[warp];
#pragma unroll
        for (int b = 0; b < B_GRAPHS; b++)
            d_h1[b * 512 + warp] = fmaxf(acc[b] + bi, 0.0f);
    }
}

// =================================================================================
// 8. fc2: one warp per (graph, output)
// =================================================================================
__global__ void __launch_bounds__(1024) k_fc2(const float* __restrict__ w,
                                              const float* __restrict__ bias,
                                              float* __restrict__ out) {
    int gw   = (blockIdx.x * blockDim.x + threadIdx.x) >> 5;  // 0..159
    int lane = threadIdx.x & 31;
    if (gw >= B_GRAPHS * OUT_DIM) return;
    int b = gw / OUT_DIM, k = gw % OUT_DIM;
    float s = 0.0f;
#pragma unroll
    for (int i = 0; i < 512 / 32; i++) {
        int o = i * 32 + lane;
        s = fmaf(d_h1[b * 512 + o], w[k * 512 + o], s);
    }
    s += __shfl_xor_sync(0xffffffffu, s, 16);
    s += __shfl_xor_sync(0xffffffffu, s, 8);
    s += __shfl_xor_sync(0xffffffffu, s, 4);
    s += __shfl_xor_sync(0xffffffffu, s, 2);
    s += __shfl_xor_sync(0xffffffffu, s, 1);
    if (lane == 0) out[b * OUT_DIM + k] = s + bias[k];
}

// ---------------- launch ----------------------------------------------------------
extern "C" void kernel_launch(void* const* d_in, const int* in_sizes, int n_in,
                              void* d_out, int out_size) {
    const float* x      = (const float*)d_in[0];
    const float* w_att  = (const float*)d_in[1];
    const float* wscale = (const float*)d_in[2];
    const float* wtrans = (const float*)d_in[3];
    const float* wwav   = (const float*)d_in[4];
    const float* wbase  = (const float*)d_in[5];
    const float* fc1w   = (const float*)d_in[6];
    const float* fc1b   = (const float*)d_in[7];
    const float* fc2w   = (const float*)d_in[8];
    const float* fc2b   = (const float*)d_in[9];
    const int*   eidx   = (const int*)d_in[10];
    const int*   batch  = (const int*)d_in[11];
    float*       out    = (float*)d_out;

    k_setup<<<898, 1024>>>(x, w_att, wscale, wtrans, wwav, wbase, eidx, batch); // #1
    k_stats_x<<<96, 256>>>(x);                                        // #2
    k_gather<<<N_NODES, 128>>>();                                     // #3
    k_wavbase<<<dim3(H_DIM / 128, N_NODES / RN, SPLIT), 128>>>();     // #4 (profiled)
    k_stats_conv<<<48, 256>>>();                                      // #5
    k_poolfinal<<<24, 1024>>>();                                      // #6
    k_fc1<<<64, 256>>>(fc1w, fc1b);                                   // #7
    k_fc2<<<5, 1024>>>(fc2w, fc2b, out);                              // #8
}

// round 15
// speedup vs baseline: 1.4813x; 1.0231x over previous
#include <cuda_runtime.h>
#include <cstdint>

#define N_NODES 1024
#define F_DIM   1024
#define H_DIM   512
#define E_EDGES 32768
#define B_GRAPHS 16
#define OUT_DIM 10
#define Z_DIM   (F_DIM + H_DIM)   // 1536
#define EPSB    1e-5f
#define MH_Cf   0.8673250705840776f
#define NEG_HALF_LOG2E (-0.7213475204444817f)
#define LOG2E   1.4426950408889634f
#define INV_SQRT2 0.7071067811865476f
#define RN 16                      // nodes per wavbase block
#define NPAIR (RN / 2)             // 8
#define SPLIT 8                    // i-dimension split factor
#define ISPLIT (H_DIM / SPLIT)     // 64 i's per block

// ---------------- scratch (static device memory; no allocations) ----------------
__device__ __align__(16) float  d_h   [N_NODES * H_DIM];
__device__ __align__(16) float  d_agg [N_NODES * H_DIM];
__device__ __align__(16) float4 d_wpack[H_DIM * H_DIM];   // [i][o] = {invS, -T*invS, C*Wwav, Wbase}
__device__ __align__(16) float  d_conv[N_NODES * H_DIM];  // wav+base (RED-accumulated)
__device__ float d_mu [Z_DIM];
__device__ float d_sc [Z_DIM];
__device__ float d_gsum[B_GRAPHS * Z_DIM];
__device__ __align__(16) float d_pooled_t[Z_DIM * B_GRAPHS];  // [j][b] transposed pooled
__device__ float d_h1 [B_GRAPHS * 512];
// CSR scratch
__device__ int d_off [N_NODES + 1];
__device__ int d_elist[E_EDGES];
__device__ int d_roff[B_GRAPHS + 1];   // per-graph node ranges (batch is sorted)

__device__ __forceinline__ float ex2f(float x) {
    float r; asm("ex2.approx.ftz.f32 %0, %1;" : "=f"(r) : "f"(x)); return r;
}
__device__ __forceinline__ float fsigmoid(float t) {
    return 1.0f / (1.0f + ex2f(-t * LOG2E));
}

// ---- f32x2 packed-math helpers (sm_103a) ----
typedef unsigned long long u64;
__device__ __forceinline__ u64 pack2(float lo, float hi) {
    u64 r; asm("mov.b64 %0, {%1, %2};" : "=l"(r) : "f"(lo), "f"(hi)); return r;
}
__device__ __forceinline__ void unpack2(u64 v, float& lo, float& hi) {
    asm("mov.b64 {%0, %1}, %2;" : "=f"(lo), "=f"(hi) : "l"(v));
}
__device__ __forceinline__ u64 fma2(u64 a, u64 b, u64 c) {
    u64 d; asm("fma.rn.f32x2 %0, %1, %2, %3;" : "=l"(d) : "l"(a), "l"(b), "l"(c)); return d;
}
__device__ __forceinline__ u64 mul2(u64 a, u64 b) {
    u64 d; asm("mul.rn.f32x2 %0, %1, %2;" : "=l"(d) : "l"(a), "l"(b)); return d;
}

__device__ __forceinline__ int lower_bound_batch(const int* batch, int key) {
    int lo = 0, hi = N_NODES;
    while (lo < hi) {
        int mid = (lo + hi) >> 1;
        if (batch[mid] < key) lo = mid + 1; else hi = mid;
    }
    return lo;
}

// =================================================================================
// 1. setup (1024-thread blocks, role by blockIdx.x):
//    [0,255]   : wpack tile transpose (coalesced via smem)
//    [256,767] : h
//    768       : CSR build
//    769       : graph ranges
//    [770,897] : zero d_conv
//    [898,929] : colstats over x columns  (was k_stats_x part 1)
//    [930,945] : pool sums over x columns (was k_stats_x part 2; binary-search ranges)
// =================================================================================
__global__ void __launch_bounds__(1024) k_setup(
        const float* __restrict__ x,      const float* __restrict__ watt,
        const float* __restrict__ scale,  const float* __restrict__ trans,
        const float* __restrict__ wavw,   const float* __restrict__ basew,
        const int*   __restrict__ ei,     const int*   __restrict__ batch) {
    __shared__ __align__(16) char sraw[17008];
    int blk = blockIdx.x, t = threadIdx.x;

    if (blk < 256) {                                // ---- wpack tile transpose ----
        float4 (*tile)[33] = reinterpret_cast<float4(*)[33]>(sraw);
        int ot = blk >> 4, it = blk & 15;           // 16x16 tiles of 32x32
        int oo = t >> 5, ii = t & 31;
        int o = ot * 32 + oo, i = it * 32 + ii;
        int idx = o * H_DIM + i;                    // coalesced read (ii fast)
        float invS = 1.0f / scale[idx];
        tile[ii][oo] = make_float4(invS, -trans[idx] * invS,
                                   MH_Cf * wavw[idx], basew[idx]);
        __syncthreads();
        int ii2 = t >> 5, oo2 = t & 31;
        d_wpack[(it * 32 + ii2) * H_DIM + (ot * 32 + oo2)] = tile[ii2][oo2]; // coalesced write
        return;
    }
    if (blk < 768) {                                // ---- h ----
        int idx = (blk - 256) * 1024 + t;           // n*H + j
        int n = idx >> 9, j = idx & 511;
        float2 p = reinterpret_cast<const float2*>(x)[n * (F_DIM / 2) + j];
        float lo = (p.x + p.y) * INV_SQRT2;
        float hi = (p.x - p.y) * INV_SQRT2;
        float s  = fsigmoid(lo * watt[0] + hi * watt[1]);
        d_h[idx] = hi + s * (lo - hi);
        return;
    }
    if (blk == 768) {                               // ---- CSR build ----
        int* s    = reinterpret_cast<int*>(sraw);
        int* wsum = reinterpret_cast<int*>(sraw + 4096);
        s[t] = 0;
        __syncthreads();
        for (int e = t; e < E_EDGES; e += 1024)
            atomicAdd(&s[ei[E_EDGES + e]], 1);
        __syncthreads();
        int v = s[t];
        int lane = t & 31, wid = t >> 5;
        int inc = v;
#pragma unroll
        for (int d = 1; d < 32; d <<= 1) {
            int up = __shfl_up_sync(0xffffffffu, inc, d);
            if (lane >= d) inc += up;
        }
        if (lane == 31) wsum[wid] = inc;
        __syncthreads();
        if (wid == 0) {
            int wv = wsum[lane];
            int winc = wv;
#pragma unroll
            for (int d = 1; d < 32; d <<= 1) {
                int up = __shfl_up_sync(0xffffffffu, winc, d);
                if (lane >= d) winc += up;
            }
            wsum[lane] = winc - wv;
        }
        __syncthreads();
        int excl = wsum[wid] + inc - v;
        d_off[t] = excl;
        if (t == N_NODES - 1) d_off[N_NODES] = excl + v;
        __syncthreads();
        s[t] = excl;
        __syncthreads();
        for (int e = t; e < E_EDGES; e += 1024) {
            int dst = ei[E_EDGES + e];
            int pos = atomicAdd(&s[dst], 1);
            d_elist[pos] = ei[e];
        }
        return;
    }
    if (blk == 769) {                               // ---- graph ranges ----
        int* rs = reinterpret_cast<int*>(sraw);
        if (t <= B_GRAPHS) rs[t] = -1;
        __syncthreads();
        for (int n = t; n < N_NODES; n += 1024) {
            int b = batch[n];
            if (n == 0 || batch[n - 1] != b) rs[b] = n;
        }
        __syncthreads();
        if (t == 0) {
            rs[B_GRAPHS] = N_NODES;
            for (int b = B_GRAPHS - 1; b >= 0; b--)
                if (rs[b] < 0) rs[b] = rs[b + 1];
            for (int b = 0; b <= B_GRAPHS; b++) d_roff[b] = rs[b];
        }
        return;
    }
    if (blk < 898) {                                // ---- zero d_conv ----
        int idx = (blk - 770) * 1024 + t;
        reinterpret_cast<float4*>(d_conv)[idx] = make_float4(0.f, 0.f, 0.f, 0.f);
        return;
    }
    if (blk < 930) {                                // ---- colstats over x ----
        float* ssum = reinterpret_cast<float*>(sraw);          // [32][32]
        float* ssq  = reinterpret_cast<float*>(sraw + 4096);   // [32][32]
        int c = t & 31, r = t >> 5;                 // r in 0..31
        int j = (blk - 898) * 32 + c;
        float s = 0.0f, q = 0.0f;
        for (int n = r; n < N_NODES; n += 32) {
            float v = x[n * F_DIM + j];
            s += v; q = fmaf(v, v, q);
        }
        ssum[r * 32 + c] = s; ssq[r * 32 + c] = q;
        __syncthreads();
        if (r == 0) {
#pragma unroll
            for (int rr = 1; rr < 32; rr++) { s += ssum[rr * 32 + c]; q += ssq[rr * 32 + c]; }
            float mu  = s * (1.0f / N_NODES);
            float var = fmaxf(q * (1.0f / N_NODES) - mu * mu, 0.0f);
            d_mu[j] = mu;
            d_sc[j] = rsqrtf(var + EPSB);
        }
        return;
    }
    {                                               // ---- pool sums over x ----
        int* bounds = reinterpret_cast<int*>(sraw);
        int b = blk - 930;                          // graph 0..15
        if (t == 0) {
            bounds[0] = lower_bound_batch(batch, b);
            bounds[1] = lower_bound_batch(batch, b + 1);
        }
        __syncthreads();
        int beg = bounds[0], end = bounds[1];
        int j = t;                                  // 0..1023 x columns
        float s = 0.0f;
        int n = beg;
        for (; n + 4 <= end; n += 4) {
            float v0 = x[n * F_DIM + j];
            float v1 = x[(n + 1) * F_DIM + j];
            float v2 = x[(n + 2) * F_DIM + j];
            float v3 = x[(n + 3) * F_DIM + j];
            s += (v0 + v1) + (v2 + v3);
        }
        for (; n < end; n++) s += x[n * F_DIM + j];
        d_gsum[b * Z_DIM + j] = s;
    }
}

// =================================================================================
// 2. gather: agg[n] = h[n] + sum_{e: dst=n} h[src]
// =================================================================================
__global__ void __launch_bounds__(128) k_gather() {
    __shared__ int se[128];
    int n = blockIdx.x, t = threadIdx.x;
    int beg = d_off[n], end = d_off[n + 1];
    float4 acc = reinterpret_cast<const float4*>(d_h + n * H_DIM)[t];
    for (int t0 = beg; t0 < end; t0 += 128) {
        int cnt = min(128, end - t0);
        if (t < cnt) se[t] = d_elist[t0 + t];
        __syncthreads();
        int k = 0;
        for (; k + 4 <= cnt; k += 4) {
            float4 v0 = reinterpret_cast<const float4*>(d_h + se[k]     * H_DIM)[t];
            float4 v1 = reinterpret_cast<const float4*>(d_h + se[k + 1] * H_DIM)[t];
            float4 v2 = reinterpret_cast<const float4*>(d_h + se[k + 2] * H_DIM)[t];
            float4 v3 = reinterpret_cast<const float4*>(d_h + se[k + 3] * H_DIM)[t];
            acc.x += v0.x + v1.x + v2.x + v3.x;
            acc.y += v0.y + v1.y + v2.y + v3.y;
            acc.z += v0.z + v1.z + v2.z + v3.z;
            acc.w += v0.w + v1.w + v2.w + v3.w;
        }
        for (; k < cnt; k++) {
            float4 v = reinterpret_cast<const float4*>(d_h + se[k] * H_DIM)[t];
            acc.x += v.x; acc.y += v.y; acc.z += v.z; acc.w += v.w;
        }
        __syncthreads();
    }
    reinterpret_cast<float4*>(d_agg + n * H_DIM)[t] = acc;
}

// =================================================================================
// 3. main loop: wav + base, packed f32x2, RN=16/SPLIT=8, RED into d_conv
// =================================================================================
__global__ void __launch_bounds__(128) k_wavbase() {
    __shared__ ulonglong2 s_pair[ISPLIT * NPAIR];     // [i_local][p] = {agg01, sa01}
    float* s_f = reinterpret_cast<float*>(s_pair);
    int t  = threadIdx.x;
    int o  = blockIdx.x * 128 + t;
    int n0 = blockIdx.y * RN;
    int i0 = blockIdx.z * ISPLIT;

    for (int idx = t; idx < (ISPLIT / 4) * RN; idx += 128) {
        int c = idx / RN;
        int n = idx % RN;
        float4 a4 = *reinterpret_cast<const float4*>(&d_agg[(n0 + n) * H_DIM + i0 + c * 4]);
        int p = n >> 1, half = n & 1;
        float av[4] = {a4.x, a4.y, a4.z, a4.w};
#pragma unroll
        for (int d = 0; d < 4; d++) {
            int i = c * 4 + d;
            float a  = av[d];
            float sa = a * fsigmoid(a);
            int base = (i * NPAIR + p) * 4;
            s_f[base + half]     = a;
            s_f[base + 2 + half] = sa;
        }
    }
    __syncthreads();

    u64 acc[NPAIR];
#pragma unroll
    for (int p = 0; p < NPAIR; p++) acc[p] = 0ull;
    const u64 cc2 = pack2(NEG_HALF_LOG2E, NEG_HALF_LOG2E);

    for (int i = 0; i < ISPLIT; i++) {
        float4 w = __ldg(&d_wpack[(i0 + i) * H_DIM + o]); // {invS, -T*invS, C*Ww, Wb}
        u64 wx2 = pack2(w.x, w.x);
        u64 wy2 = pack2(w.y, w.y);
        float nz = -w.z;
        u64 nwz2 = pack2(nz, nz);
        u64 wz2  = pack2(w.z, w.z);
        u64 ww2  = pack2(w.w, w.w);
        const ulonglong2* row = &s_pair[i * NPAIR];
#pragma unroll
        for (int p = 0; p < NPAIR; p++) {
            ulonglong2 v = row[p];
            u64 u   = fma2(v.x, wx2, wy2);
            u64 tt  = mul2(u, u);
            u64 arg = mul2(tt, cc2);
            float alo, ahi; unpack2(arg, alo, ahi);
            u64 e   = pack2(ex2f(alo), ex2f(ahi));
            u64 g   = fma2(tt, nwz2, wz2);
            acc[p]  = fma2(v.y, ww2, acc[p]);
            acc[p]  = fma2(g, e, acc[p]);
        }
    }
#pragma unroll
    for (int p = 0; p < NPAIR; p++) {
        float w0, w1;
        unpack2(acc[p], w0, w1);
        atomicAdd(&d_conv[(n0 + 2 * p)     * H_DIM + o], w0);
        atomicAdd(&d_conv[(n0 + 2 * p + 1) * H_DIM + o], w1);
    }
}

// =================================================================================
// 4. stats over conv columns (launch #4 — profiled):
//    blocks [0,15]  : colstats with triple-bn fold
//    blocks [16,47] : pool sums (atomic-free)
// =================================================================================
__global__ void __launch_bounds__(256) k_stats_conv() {
    int blk = blockIdx.x, t = threadIdx.x;
    if (blk < 16) {
        __shared__ float ssum[8][32], ssq[8][32];
        int c = t & 31, r = t >> 5;
        int col = blk * 32 + c;
        int j = F_DIM + col;
        float s = 0.0f, q = 0.0f;
        for (int n = r; n < N_NODES; n += 8) {
            float v = d_conv[n * H_DIM + col];
            s += v; q = fmaf(v, v, q);
        }
        ssum[r][c] = s; ssq[r][c] = q;
        __syncthreads();
        if (r == 0) {
#pragma unroll
            for (int rr = 1; rr < 8; rr++) { s += ssum[rr][c]; q += ssq[rr][c]; }
            float mu  = s * (1.0f / N_NODES);
            float var = fmaxf(q * (1.0f / N_NODES) - mu * mu, 0.0f);
            float a1 = rsqrtf(var + EPSB);
            float v1 = var / (var + EPSB);
            float a2 = rsqrtf(v1 + EPSB);
            float v2 = v1 / (v1 + EPSB);
            float a3 = rsqrtf(v2 + EPSB);
            d_mu[j] = mu;
            d_sc[j] = a1 * a2 * a3;
        }
        return;
    }
    {
        int w   = blk - 16;
        int b   = w >> 1;
        int ch  = w & 1;
        int col = ch * 256 + t;
        int j   = F_DIM + col;
        int beg = d_roff[b], end = d_roff[b + 1];
        float s = 0.0f;
        int n = beg;
        for (; n + 4 <= end; n += 4) {
            float v0 = d_conv[n * H_DIM + col];
            float v1 = d_conv[(n + 1) * H_DIM + col];
            float v2 = d_conv[(n + 2) * H_DIM + col];
            float v3 = d_conv[(n + 3) * H_DIM + col];
            s += (v0 + v1) + (v2 + v3);
        }
        for (; n < end; n++) s += d_conv[n * H_DIM + col];
        d_gsum[b * Z_DIM + j] = s;
    }
}

// =================================================================================
// 5. poolfinal: pooled_t[j][b] = (gsum[b][j]/cnt_b - mu_j) * sc_j  (transposed)
// =================================================================================
__global__ void __launch_bounds__(1024) k_poolfinal() {
    int idx = blockIdx.x * 1024 + threadIdx.x;        // j*16 + b
    if (idx >= Z_DIM * B_GRAPHS) return;
    int j = idx >> 4, b = idx & 15;
    int c = d_roff[b + 1] - d_roff[b];
    float pooled = 0.0f;
    if (c > 0)
        pooled = (d_gsum[b * Z_DIM + j] / (float)c - d_mu[j]) * d_sc[j];
    d_pooled_t[idx] = pooled;
}

// =================================================================================
// 6. fc1 + relu: 64 blocks x 256 thr, warp-per-output, vectorized pooled_t loads
// =================================================================================
__global__ void __launch_bounds__(256) k_fc1(const float* __restrict__ w,
                                             const float* __restrict__ bias) {
    int warp = blockIdx.x * 8 + (threadIdx.x >> 5);   // 0..511 = o
    int lane = threadIdx.x & 31;
    float acc[B_GRAPHS];
#pragma unroll
    for (int b = 0; b < B_GRAPHS; b++) acc[b] = 0.0f;
    for (int k0 = 0; k0 < Z_DIM; k0 += 32) {
        int j = k0 + lane;
        float wv = w[warp * Z_DIM + j];
        const float4* pt = reinterpret_cast<const float4*>(&d_pooled_t[j * B_GRAPHS]);
#pragma unroll
        for (int qq = 0; qq < 4; qq++) {
            float4 p4 = pt[qq];
            acc[qq * 4 + 0] = fmaf(wv, p4.x, acc[qq * 4 + 0]);
            acc[qq * 4 + 1] = fmaf(wv, p4.y, acc[qq * 4 + 1]);
            acc[qq * 4 + 2] = fmaf(wv, p4.z, acc[qq * 4 + 2]);
            acc[qq * 4 + 3] = fmaf(wv, p4.w, acc[qq * 4 + 3]);
        }
    }
#pragma unroll
    for (int b = 0; b < B_GRAPHS; b++) {
        float s = acc[b];
        s += __shfl_xor_sync(0xffffffffu, s, 16);
        s += __shfl_xor_sync(0xffffffffu, s, 8);
        s += __shfl_xor_sync(0xffffffffu, s, 4);
        s += __shfl_xor_sync(0xffffffffu, s, 2);
        s += __shfl_xor_sync(0xffffffffu, s, 1);
        acc[b] = s;
    }
    if (lane == 0) {
        float bi = bias[warp];
#pragma unroll
        for (int b = 0; b < B_GRAPHS; b++)
            d_h1[b * 512 + warp] = fmaxf(acc[b] + bi, 0.0f);
    }
}

// =================================================================================
// 7. fc2: one warp per (graph, output)
// =================================================================================
__global__ void __launch_bounds__(1024) k_fc2(const float* __restrict__ w,
                                              const float* __restrict__ bias,
                                              float* __restrict__ out) {
    int gw   = (blockIdx.x * blockDim.x + threadIdx.x) >> 5;  // 0..159
    int lane = threadIdx.x & 31;
    if (gw >= B_GRAPHS * OUT_DIM) return;
    int b = gw / OUT_DIM, k = gw % OUT_DIM;
    float s = 0.0f;
#pragma unroll
    for (int i = 0; i < 512 / 32; i++) {
        int o = i * 32 + lane;
        s = fmaf(d_h1[b * 512 + o], w[k * 512 + o], s);
    }
    s += __shfl_xor_sync(0xffffffffu, s, 16);
    s += __shfl_xor_sync(0xffffffffu, s, 8);
    s += __shfl_xor_sync(0xffffffffu, s, 4);
    s += __shfl_xor_sync(0xffffffffu, s, 2);
    s += __shfl_xor_sync(0xffffffffu, s, 1);
    if (lane == 0) out[b * OUT_DIM + k] = s + bias[k];
}

// ---------------- launch ----------------------------------------------------------
extern "C" void kernel_launch(void* const* d_in, const int* in_sizes, int n_in,
                              void* d_out, int out_size) {
    const float* x      = (const float*)d_in[0];
    const float* w_att  = (const float*)d_in[1];
    const float* wscale = (const float*)d_in[2];
    const float* wtrans = (const float*)d_in[3];
    const float* wwav   = (const float*)d_in[4];
    const float* wbase  = (const float*)d_in[5];
    const float* fc1w   = (const float*)d_in[6];
    const float* fc1b   = (const float*)d_in[7];
    const float* fc2w   = (const float*)d_in[8];
    const float* fc2b   = (const float*)d_in[9];
    const int*   eidx   = (const int*)d_in[10];
    const int*   batch  = (const int*)d_in[11];
    float*       out    = (float*)d_out;

    k_setup<<<946, 1024>>>(x, w_att, wscale, wtrans, wwav, wbase, eidx, batch); // #1
    k_gather<<<N_NODES, 128>>>();                                     // #2
    k_wavbase<<<dim3(H_DIM / 128, N_NODES / RN, SPLIT), 128>>>();     // #3
    k_stats_conv<<<48, 256>>>();                                      // #4 (profiled)
    k_poolfinal<<<24, 1024>>>();                                      // #5
    k_fc1<<<64, 256>>>(fc1w, fc1b);                                   // #6
    k_fc2<<<5, 1024>>>(fc2w, fc2b, out);                              // #7
}

// round 16
// speedup vs baseline: 1.5247x; 1.0293x over previous
#include <cuda_runtime.h>
#include <cstdint>

#define N_NODES 1024
#define F_DIM   1024
#define H_DIM   512
#define E_EDGES 32768
#define B_GRAPHS 16
#define OUT_DIM 10
#define Z_DIM   (F_DIM + H_DIM)   // 1536
#define EPSB    1e-5f
#define MH_Cf   0.8673250705840776f
#define NEG_HALF_LOG2E (-0.7213475204444817f)
#define LOG2E   1.4426950408889634f
#define INV_SQRT2 0.7071067811865476f
#define RN 16                      // nodes per wavbase block
#define NPAIR (RN / 2)             // 8
#define SPLIT 8                    // i-dimension split factor
#define ISPLIT (H_DIM / SPLIT)     // 64 i's per block

// ---------------- scratch (static device memory; no allocations) ----------------
__device__ __align__(16) float  d_h   [N_NODES * H_DIM];
__device__ __align__(16) float  d_agg [N_NODES * H_DIM];
__device__ __align__(16) float4 d_wpack[H_DIM * H_DIM];   // [i][o] = {invS, -T*invS, C*Wwav, Wbase}
__device__ __align__(16) float  d_conv[N_NODES * H_DIM];  // wav+base (RED-accumulated)
__device__ float d_mu [Z_DIM];
__device__ float d_sc [Z_DIM];
__device__ float d_gsum[B_GRAPHS * Z_DIM];
__device__ __align__(16) float d_pooled_t[Z_DIM * B_GRAPHS];  // [j][b] transposed pooled
__device__ float d_h1 [B_GRAPHS * 512];
// CSR scratch
__device__ int d_off [N_NODES + 1];
__device__ int d_elist[E_EDGES];
__device__ int d_roff[B_GRAPHS + 1];   // per-graph node ranges (batch is sorted)

__device__ __forceinline__ float ex2f(float x) {
    float r; asm("ex2.approx.ftz.f32 %0, %1;" : "=f"(r) : "f"(x)); return r;
}
__device__ __forceinline__ float fsigmoid(float t) {
    return 1.0f / (1.0f + ex2f(-t * LOG2E));
}

// ---- f32x2 packed-math helpers (sm_103a) ----
typedef unsigned long long u64;
__device__ __forceinline__ u64 pack2(float lo, float hi) {
    u64 r; asm("mov.b64 %0, {%1, %2};" : "=l"(r) : "f"(lo), "f"(hi)); return r;
}
__device__ __forceinline__ void unpack2(u64 v, float& lo, float& hi) {
    asm("mov.b64 {%0, %1}, %2;" : "=f"(lo), "=f"(hi) : "l"(v));
}
__device__ __forceinline__ u64 fma2(u64 a, u64 b, u64 c) {
    u64 d; asm("fma.rn.f32x2 %0, %1, %2, %3;" : "=l"(d) : "l"(a), "l"(b), "l"(c)); return d;
}
__device__ __forceinline__ u64 mul2(u64 a, u64 b) {
    u64 d; asm("mul.rn.f32x2 %0, %1, %2;" : "=l"(d) : "l"(a), "l"(b)); return d;
}

__device__ __forceinline__ int lower_bound_batch(const int* batch, int key) {
    int lo = 0, hi = N_NODES;
    while (lo < hi) {
        int mid = (lo + hi) >> 1;
        if (batch[mid] < key) lo = mid + 1; else hi = mid;
    }
    return lo;
}

// =================================================================================
// 1. setup (1024-thread blocks, role by blockIdx.x):
//    [0,255]   : wpack tile transpose (coalesced via smem)
//    [256,767] : h
//    768       : CSR build
//    769       : graph ranges
//    [770,897] : zero d_conv
//    [898,929] : colstats over x columns
//    [930,945] : pool sums over x columns (binary-search ranges)
// =================================================================================
__global__ void __launch_bounds__(1024) k_setup(
        const float* __restrict__ x,      const float* __restrict__ watt,
        const float* __restrict__ scale,  const float* __restrict__ trans,
        const float* __restrict__ wavw,   const float* __restrict__ basew,
        const int*   __restrict__ ei,     const int*   __restrict__ batch) {
    __shared__ __align__(16) char sraw[17008];
    int blk = blockIdx.x, t = threadIdx.x;

    if (blk < 256) {                                // ---- wpack tile transpose ----
        float4 (*tile)[33] = reinterpret_cast<float4(*)[33]>(sraw);
        int ot = blk >> 4, it = blk & 15;           // 16x16 tiles of 32x32
        int oo = t >> 5, ii = t & 31;
        int o = ot * 32 + oo, i = it * 32 + ii;
        int idx = o * H_DIM + i;                    // coalesced read (ii fast)
        float invS = 1.0f / scale[idx];
        tile[ii][oo] = make_float4(invS, -trans[idx] * invS,
                                   MH_Cf * wavw[idx], basew[idx]);
        __syncthreads();
        int ii2 = t >> 5, oo2 = t & 31;
        d_wpack[(it * 32 + ii2) * H_DIM + (ot * 32 + oo2)] = tile[ii2][oo2]; // coalesced write
        return;
    }
    if (blk < 768) {                                // ---- h ----
        int idx = (blk - 256) * 1024 + t;           // n*H + j
        int n = idx >> 9, j = idx & 511;
        float2 p = reinterpret_cast<const float2*>(x)[n * (F_DIM / 2) + j];
        float lo = (p.x + p.y) * INV_SQRT2;
        float hi = (p.x - p.y) * INV_SQRT2;
        float s  = fsigmoid(lo * watt[0] + hi * watt[1]);
        d_h[idx] = hi + s * (lo - hi);
        return;
    }
    if (blk == 768) {                               // ---- CSR build ----
        int* s    = reinterpret_cast<int*>(sraw);
        int* wsum = reinterpret_cast<int*>(sraw + 4096);
        s[t] = 0;
        __syncthreads();
        for (int e = t; e < E_EDGES; e += 1024)
            atomicAdd(&s[ei[E_EDGES + e]], 1);
        __syncthreads();
        int v = s[t];
        int lane = t & 31, wid = t >> 5;
        int inc = v;
#pragma unroll
        for (int d = 1; d < 32; d <<= 1) {
            int up = __shfl_up_sync(0xffffffffu, inc, d);
            if (lane >= d) inc += up;
        }
        if (lane == 31) wsum[wid] = inc;
        __syncthreads();
        if (wid == 0) {
            int wv = wsum[lane];
            int winc = wv;
#pragma unroll
            for (int d = 1; d < 32; d <<= 1) {
                int up = __shfl_up_sync(0xffffffffu, winc, d);
                if (lane >= d) winc += up;
            }
            wsum[lane] = winc - wv;
        }
        __syncthreads();
        int excl = wsum[wid] + inc - v;
        d_off[t] = excl;
        if (t == N_NODES - 1) d_off[N_NODES] = excl + v;
        __syncthreads();
        s[t] = excl;
        __syncthreads();
        for (int e = t; e < E_EDGES; e += 1024) {
            int dst = ei[E_EDGES + e];
            int pos = atomicAdd(&s[dst], 1);
            d_elist[pos] = ei[e];
        }
        return;
    }
    if (blk == 769) {                               // ---- graph ranges ----
        int* rs = reinterpret_cast<int*>(sraw);
        if (t <= B_GRAPHS) rs[t] = -1;
        __syncthreads();
        for (int n = t; n < N_NODES; n += 1024) {
            int b = batch[n];
            if (n == 0 || batch[n - 1] != b) rs[b] = n;
        }
        __syncthreads();
        if (t == 0) {
            rs[B_GRAPHS] = N_NODES;
            for (int b = B_GRAPHS - 1; b >= 0; b--)
                if (rs[b] < 0) rs[b] = rs[b + 1];
            for (int b = 0; b <= B_GRAPHS; b++) d_roff[b] = rs[b];
        }
        return;
    }
    if (blk < 898) {                                // ---- zero d_conv ----
        int idx = (blk - 770) * 1024 + t;
        reinterpret_cast<float4*>(d_conv)[idx] = make_float4(0.f, 0.f, 0.f, 0.f);
        return;
    }
    if (blk < 930) {                                // ---- colstats over x ----
        float* ssum = reinterpret_cast<float*>(sraw);          // [32][32]
        float* ssq  = reinterpret_cast<float*>(sraw + 4096);   // [32][32]
        int c = t & 31, r = t >> 5;                 // r in 0..31
        int j = (blk - 898) * 32 + c;
        float s = 0.0f, q = 0.0f;
        for (int n = r; n < N_NODES; n += 32) {
            float v = x[n * F_DIM + j];
            s += v; q = fmaf(v, v, q);
        }
        ssum[r * 32 + c] = s; ssq[r * 32 + c] = q;
        __syncthreads();
        if (r == 0) {
#pragma unroll
            for (int rr = 1; rr < 32; rr++) { s += ssum[rr * 32 + c]; q += ssq[rr * 32 + c]; }
            float mu  = s * (1.0f / N_NODES);
            float var = fmaxf(q * (1.0f / N_NODES) - mu * mu, 0.0f);
            d_mu[j] = mu;
            d_sc[j] = rsqrtf(var + EPSB);
        }
        return;
    }
    {                                               // ---- pool sums over x ----
        int* bounds = reinterpret_cast<int*>(sraw);
        int b = blk - 930;                          // graph 0..15
        if (t == 0) {
            bounds[0] = lower_bound_batch(batch, b);
            bounds[1] = lower_bound_batch(batch, b + 1);
        }
        __syncthreads();
        int beg = bounds[0], end = bounds[1];
        int j = t;                                  // 0..1023 x columns
        float s = 0.0f;
        int n = beg;
        for (; n + 4 <= end; n += 4) {
            float v0 = x[n * F_DIM + j];
            float v1 = x[(n + 1) * F_DIM + j];
            float v2 = x[(n + 2) * F_DIM + j];
            float v3 = x[(n + 3) * F_DIM + j];
            s += (v0 + v1) + (v2 + v3);
        }
        for (; n < end; n++) s += x[n * F_DIM + j];
        d_gsum[b * Z_DIM + j] = s;
    }
}

// =================================================================================
// 2. gather: agg[n] = h[n] + sum_{e: dst=n} h[src]
// =================================================================================
__global__ void __launch_bounds__(128) k_gather() {
    __shared__ int se[128];
    int n = blockIdx.x, t = threadIdx.x;
    int beg = d_off[n], end = d_off[n + 1];
    float4 acc = reinterpret_cast<const float4*>(d_h + n * H_DIM)[t];
    for (int t0 = beg; t0 < end; t0 += 128) {
        int cnt = min(128, end - t0);
        if (t < cnt) se[t] = d_elist[t0 + t];
        __syncthreads();
        int k = 0;
        for (; k + 4 <= cnt; k += 4) {
            float4 v0 = reinterpret_cast<const float4*>(d_h + se[k]     * H_DIM)[t];
            float4 v1 = reinterpret_cast<const float4*>(d_h + se[k + 1] * H_DIM)[t];
            float4 v2 = reinterpret_cast<const float4*>(d_h + se[k + 2] * H_DIM)[t];
            float4 v3 = reinterpret_cast<const float4*>(d_h + se[k + 3] * H_DIM)[t];
            acc.x += v0.x + v1.x + v2.x + v3.x;
            acc.y += v0.y + v1.y + v2.y + v3.y;
            acc.z += v0.z + v1.z + v2.z + v3.z;
            acc.w += v0.w + v1.w + v2.w + v3.w;
        }
        for (; k < cnt; k++) {
            float4 v = reinterpret_cast<const float4*>(d_h + se[k] * H_DIM)[t];
            acc.x += v.x; acc.y += v.y; acc.z += v.z; acc.w += v.w;
        }
        __syncthreads();
    }
    reinterpret_cast<float4*>(d_agg + n * H_DIM)[t] = acc;
}

// =================================================================================
// 3. main loop: wav + base, packed f32x2, RN=16/SPLIT=8, RED into d_conv
// =================================================================================
__global__ void __launch_bounds__(128) k_wavbase() {
    __shared__ ulonglong2 s_pair[ISPLIT * NPAIR];     // [i_local][p] = {agg01, sa01}
    float* s_f = reinterpret_cast<float*>(s_pair);
    int t  = threadIdx.x;
    int o  = blockIdx.x * 128 + t;
    int n0 = blockIdx.y * RN;
    int i0 = blockIdx.z * ISPLIT;

    for (int idx = t; idx < (ISPLIT / 4) * RN; idx += 128) {
        int c = idx / RN;
        int n = idx % RN;
        float4 a4 = *reinterpret_cast<const float4*>(&d_agg[(n0 + n) * H_DIM + i0 + c * 4]);
        int p = n >> 1, half = n & 1;
        float av[4] = {a4.x, a4.y, a4.z, a4.w};
#pragma unroll
        for (int d = 0; d < 4; d++) {
            int i = c * 4 + d;
            float a  = av[d];
            float sa = a * fsigmoid(a);
            int base = (i * NPAIR + p) * 4;
            s_f[base + half]     = a;
            s_f[base + 2 + half] = sa;
        }
    }
    __syncthreads();

    u64 acc[NPAIR];
#pragma unroll
    for (int p = 0; p < NPAIR; p++) acc[p] = 0ull;
    const u64 cc2 = pack2(NEG_HALF_LOG2E, NEG_HALF_LOG2E);

    for (int i = 0; i < ISPLIT; i++) {
        float4 w = __ldg(&d_wpack[(i0 + i) * H_DIM + o]); // {invS, -T*invS, C*Ww, Wb}
        u64 wx2 = pack2(w.x, w.x);
        u64 wy2 = pack2(w.y, w.y);
        float nz = -w.z;
        u64 nwz2 = pack2(nz, nz);
        u64 wz2  = pack2(w.z, w.z);
        u64 ww2  = pack2(w.w, w.w);
        const ulonglong2* row = &s_pair[i * NPAIR];
#pragma unroll
        for (int p = 0; p < NPAIR; p++) {
            ulonglong2 v = row[p];
            u64 u   = fma2(v.x, wx2, wy2);
            u64 tt  = mul2(u, u);
            u64 arg = mul2(tt, cc2);
            float alo, ahi; unpack2(arg, alo, ahi);
            u64 e   = pack2(ex2f(alo), ex2f(ahi));
            u64 g   = fma2(tt, nwz2, wz2);
            acc[p]  = fma2(v.y, ww2, acc[p]);
            acc[p]  = fma2(g, e, acc[p]);
        }
    }
#pragma unroll
    for (int p = 0; p < NPAIR; p++) {
        float w0, w1;
        unpack2(acc[p], w0, w1);
        atomicAdd(&d_conv[(n0 + 2 * p)     * H_DIM + o], w0);
        atomicAdd(&d_conv[(n0 + 2 * p + 1) * H_DIM + o], w1);
    }
}

// =================================================================================
// 4. stats over conv columns (launch #4 — profiled), 1024-thread blocks:
//    blocks [0,15]  : colstats (32 cols x 32 node-strips) with triple-bn fold
//    blocks [16,47] : pool sums (256 cols x 4 range-strips)
// =================================================================================
__global__ void __launch_bounds__(1024) k_stats_conv() {
    __shared__ __align__(16) float sm[2 * 32 * 33];
    int blk = blockIdx.x, t = threadIdx.x;
    if (blk < 16) {                                   // ---- colstats (conv) ----
        float* ssum = sm;                             // [32][33]
        float* ssq  = sm + 32 * 33;
        int c = t & 31, r = t >> 5;                   // 32 strips
        int col = blk * 32 + c;
        int j = F_DIM + col;
        float s = 0.0f, q = 0.0f;
        for (int n = r; n < N_NODES; n += 32) {
            float v = d_conv[n * H_DIM + col];
            s += v; q = fmaf(v, v, q);
        }
        ssum[r * 33 + c] = s; ssq[r * 33 + c] = q;
        __syncthreads();
        if (r == 0) {
#pragma unroll
            for (int rr = 1; rr < 32; rr++) { s += ssum[rr * 33 + c]; q += ssq[rr * 33 + c]; }
            float mu  = s * (1.0f / N_NODES);
            float var = fmaxf(q * (1.0f / N_NODES) - mu * mu, 0.0f);
            float a1 = rsqrtf(var + EPSB);
            float v1 = var / (var + EPSB);
            float a2 = rsqrtf(v1 + EPSB);
            float v2 = v1 / (v1 + EPSB);
            float a3 = rsqrtf(v2 + EPSB);
            d_mu[j] = mu;
            d_sc[j] = a1 * a2 * a3;
        }
        return;
    }
    {                                                 // ---- pool sums (conv) ----
        float* part = sm;                             // [4][256]
        int w   = blk - 16;                           // 0..31
        int b   = w >> 1;
        int ch  = w & 1;
        int col = ch * 256 + (t & 255);
        int strip = t >> 8;                           // 0..3
        int j   = F_DIM + col;
        int beg = d_roff[b], end = d_roff[b + 1];
        float s = 0.0f;
        for (int n = beg + strip; n < end; n += 4)
            s += d_conv[n * H_DIM + col];
        part[strip * 256 + (t & 255)] = s;
        __syncthreads();
        if (strip == 0) {
            s += part[256 + (t & 255)] + part[512 + (t & 255)] + part[768 + (t & 255)];
            d_gsum[b * Z_DIM + j] = s;
        }
    }
}

// =================================================================================
// 5. poolfinal: pooled_t[j][b] = (gsum[b][j]/cnt_b - mu_j) * sc_j  (transposed)
// =================================================================================
__global__ void __launch_bounds__(1024) k_poolfinal() {
    int idx = blockIdx.x * 1024 + threadIdx.x;        // j*16 + b
    if (idx >= Z_DIM * B_GRAPHS) return;
    int j = idx >> 4, b = idx & 15;
    int c = d_roff[b + 1] - d_roff[b];
    float pooled = 0.0f;
    if (c > 0)
        pooled = (d_gsum[b * Z_DIM + j] / (float)c - d_mu[j]) * d_sc[j];
    d_pooled_t[idx] = pooled;
}

// =================================================================================
// 6. fc1 + relu: 64 blocks x 256 thr, warp-per-output, vectorized pooled_t loads
// =================================================================================
__global__ void __launch_bounds__(256) k_fc1(const float* __restrict__ w,
                                             const float* __restrict__ bias) {
    int warp = blockIdx.x * 8 + (threadIdx.x >> 5);   // 0..511 = o
    int lane = threadIdx.x & 31;
    float acc[B_GRAPHS];
#pragma unroll
    for (int b = 0; b < B_GRAPHS; b++) acc[b] = 0.0f;
    for (int k0 = 0; k0 < Z_DIM; k0 += 32) {
        int j = k0 + lane;
        float wv = w[warp * Z_DIM + j];
        const float4* pt = reinterpret_cast<const float4*>(&d_pooled_t[j * B_GRAPHS]);
#pragma unroll
        for (int qq = 0; qq < 4; qq++) {
            float4 p4 = pt[qq];
            acc[qq * 4 + 0] = fmaf(wv, p4.x, acc[qq * 4 + 0]);
            acc[qq * 4 + 1] = fmaf(wv, p4.y, acc[qq * 4 + 1]);
            acc[qq * 4 + 2] = fmaf(wv, p4.z, acc[qq * 4 + 2]);
            acc[qq * 4 + 3] = fmaf(wv, p4.w, acc[qq * 4 + 3]);
        }
    }
#pragma unroll
    for (int b = 0; b < B_GRAPHS; b++) {
        float s = acc[b];
        s += __shfl_xor_sync(0xffffffffu, s, 16);
        s += __shfl_xor_sync(0xffffffffu, s, 8);
        s += __shfl_xor_sync(0xffffffffu, s, 4);
        s += __shfl_xor_sync(0xffffffffu, s, 2);
        s += __shfl_xor_sync(0xffffffffu, s, 1);
        acc[b] = s;
    }
    if (lane == 0) {
        float bi = bias[warp];
#pragma unroll
        for (int b = 0; b < B_GRAPHS; b++)
            d_h1[b * 512 + warp] = fmaxf(acc[b] + bi, 0.0f);
    }
}

// =================================================================================
// 7. fc2: one warp per (graph, output)
// =================================================================================
__global__ void __launch_bounds__(1024) k_fc2(const float* __restrict__ w,
                                              const float* __restrict__ bias,
                                              float* __restrict__ out) {
    int gw   = (blockIdx.x * blockDim.x + threadIdx.x) >> 5;  // 0..159
    int lane = threadIdx.x & 31;
    if (gw >= B_GRAPHS * OUT_DIM) return;
    int b = gw / OUT_DIM, k = gw % OUT_DIM;
    float s = 0.0f;
#pragma unroll
    for (int i = 0; i < 512 / 32; i++) {
        int o = i * 32 + lane;
        s = fmaf(d_h1[b * 512 + o], w[k * 512 + o], s);
    }
    s += __shfl_xor_sync(0xffffffffu, s, 16);
    s += __shfl_xor_sync(0xffffffffu, s, 8);
    s += __shfl_xor_sync(0xffffffffu, s, 4);
    s += __shfl_xor_sync(0xffffffffu, s, 2);
    s += __shfl_xor_sync(0xffffffffu, s, 1);
    if (lane == 0) out[b * OUT_DIM + k] = s + bias[k];
}

// ---------------- launch ----------------------------------------------------------
extern "C" void kernel_launch(void* const* d_in, const int* in_sizes, int n_in,
                              void* d_out, int out_size) {
    const float* x      = (const float*)d_in[0];
    const float* w_att  = (const float*)d_in[1];
    const float* wscale = (const float*)d_in[2];
    const float* wtrans = (const float*)d_in[3];
    const float* wwav   = (const float*)d_in[4];
    const float* wbase  = (const float*)d_in[5];
    const float* fc1w   = (const float*)d_in[6];
    const float* fc1b   = (const float*)d_in[7];
    const float* fc2w   = (const float*)d_in[8];
    const float* fc2b   = (const float*)d_in[9];
    const int*   eidx   = (const int*)d_in[10];
    const int*   batch  = (const int*)d_in[11];
    float*       out    = (float*)d_out;

    k_setup<<<946, 1024>>>(x, w_att, wscale, wtrans, wwav, wbase, eidx, batch); // #1
    k_gather<<<N_NODES, 128>>>();                                     // #2
    k_wavbase<<<dim3(H_DIM / 128, N_NODES / RN, SPLIT), 128>>>();     // #3
    k_stats_conv<<<48, 1024>>>();                                     // #4 (profiled)
    k_poolfinal<<<24, 1024>>>();                                      // #5
    k_fc1<<<64, 256>>>(fc1w, fc1b);                                   // #6
    k_fc2<<<5, 1024>>>(fc2w, fc2b, out);                              // #7
}

// round 17
// speedup vs baseline: 1.5745x; 1.0327x over previous
#include <cuda_runtime.h>
#include <cstdint>

#define N_NODES 1024
#define F_DIM   1024
#define H_DIM   512
#define E_EDGES 32768
#define B_GRAPHS 16
#define OUT_DIM 10
#define Z_DIM   (F_DIM + H_DIM)   // 1536
#define EPSB    1e-5f
#define MH_Cf   0.8673250705840776f
#define NEG_HALF_LOG2E (-0.7213475204444817f)
#define LOG2E   1.4426950408889634f
#define INV_SQRT2 0.7071067811865476f
#define RN 16                      // nodes per wavbase block
#define NPAIR (RN / 2)             // 8
#define SPLIT 16                   // i-dimension split factor
#define ISPLIT (H_DIM / SPLIT)     // 32 i's per block

// ---------------- scratch (static device memory; no allocations) ----------------
__device__ __align__(16) float  d_h   [N_NODES * H_DIM];
__device__ __align__(16) float  d_agg [N_NODES * H_DIM];
__device__ __align__(16) float4 d_wpack[H_DIM * H_DIM];   // [i][o] = {invS, -T*invS, C*Wwav, Wbase}
__device__ __align__(16) float  d_conv[N_NODES * H_DIM];  // wav+base (RED-accumulated)
__device__ float d_mu [Z_DIM];
__device__ float d_sc [Z_DIM];
__device__ float d_gsum[B_GRAPHS * Z_DIM];
__device__ __align__(16) float d_pooled_t[Z_DIM * B_GRAPHS];  // [j][b] transposed pooled
__device__ float d_h1 [B_GRAPHS * 512];
// CSR scratch
__device__ int d_off [N_NODES + 1];
__device__ int d_elist[E_EDGES];
__device__ int d_roff[B_GRAPHS + 1];   // per-graph node ranges (batch is sorted)

__device__ __forceinline__ float ex2f(float x) {
    float r; asm("ex2.approx.ftz.f32 %0, %1;" : "=f"(r) : "f"(x)); return r;
}
__device__ __forceinline__ float fsigmoid(float t) {
    return 1.0f / (1.0f + ex2f(-t * LOG2E));
}

// ---- f32x2 packed-math helpers (sm_103a) ----
typedef unsigned long long u64;
__device__ __forceinline__ u64 pack2(float lo, float hi) {
    u64 r; asm("mov.b64 %0, {%1, %2};" : "=l"(r) : "f"(lo), "f"(hi)); return r;
}
__device__ __forceinline__ void unpack2(u64 v, float& lo, float& hi) {
    asm("mov.b64 {%0, %1}, %2;" : "=f"(lo), "=f"(hi) : "l"(v));
}
__device__ __forceinline__ u64 fma2(u64 a, u64 b, u64 c) {
    u64 d; asm("fma.rn.f32x2 %0, %1, %2, %3;" : "=l"(d) : "l"(a), "l"(b), "l"(c)); return d;
}
__device__ __forceinline__ u64 mul2(u64 a, u64 b) {
    u64 d; asm("mul.rn.f32x2 %0, %1, %2;" : "=l"(d) : "l"(a), "l"(b)); return d;
}

__device__ __forceinline__ int lower_bound_batch(const int* batch, int key) {
    int lo = 0, hi = N_NODES;
    while (lo < hi) {
        int mid = (lo + hi) >> 1;
        if (batch[mid] < key) lo = mid + 1; else hi = mid;
    }
    return lo;
}

// =================================================================================
// 1. setup (1024-thread blocks, role by blockIdx.x; stragglers FIRST):
//    0         : CSR build (longest single block -> starts at t=0)
//    1         : graph ranges
//    [2,257]   : wpack tile transpose (coalesced via smem)
//    [258,769] : h
//    [770,897] : zero d_conv
//    [898,929] : colstats over x columns
//    [930,945] : pool sums over x columns (binary-search ranges)
// =================================================================================
__global__ void __launch_bounds__(1024) k_setup(
        const float* __restrict__ x,      const float* __restrict__ watt,
        const float* __restrict__ scale,  const float* __restrict__ trans,
        const float* __restrict__ wavw,   const float* __restrict__ basew,
        const int*   __restrict__ ei,     const int*   __restrict__ batch) {
    __shared__ __align__(16) char sraw[17008];
    int blk = blockIdx.x, t = threadIdx.x;

    if (blk == 0) {                                 // ---- CSR build ----
        int* s    = reinterpret_cast<int*>(sraw);
        int* wsum = reinterpret_cast<int*>(sraw + 4096);
        s[t] = 0;
        __syncthreads();
        for (int e = t; e < E_EDGES; e += 1024)
            atomicAdd(&s[ei[E_EDGES + e]], 1);
        __syncthreads();
        int v = s[t];
        int lane = t & 31, wid = t >> 5;
        int inc = v;
#pragma unroll
        for (int d = 1; d < 32; d <<= 1) {
            int up = __shfl_up_sync(0xffffffffu, inc, d);
            if (lane >= d) inc += up;
        }
        if (lane == 31) wsum[wid] = inc;
        __syncthreads();
        if (wid == 0) {
            int wv = wsum[lane];
            int winc = wv;
#pragma unroll
            for (int d = 1; d < 32; d <<= 1) {
                int up = __shfl_up_sync(0xffffffffu, winc, d);
                if (lane >= d) winc += up;
            }
            wsum[lane] = winc - wv;
        }
        __syncthreads();
        int excl = wsum[wid] + inc - v;
        d_off[t] = excl;
        if (t == N_NODES - 1) d_off[N_NODES] = excl + v;
        __syncthreads();
        s[t] = excl;
        __syncthreads();
        for (int e = t; e < E_EDGES; e += 1024) {
            int dst = ei[E_EDGES + e];
            int pos = atomicAdd(&s[dst], 1);
            d_elist[pos] = ei[e];
        }
        return;
    }
    if (blk == 1) {                                 // ---- graph ranges ----
        int* rs = reinterpret_cast<int*>(sraw);
        if (t <= B_GRAPHS) rs[t] = -1;
        __syncthreads();
        for (int n = t; n < N_NODES; n += 1024) {
            int b = batch[n];
            if (n == 0 || batch[n - 1] != b) rs[b] = n;
        }
        __syncthreads();
        if (t == 0) {
            rs[B_GRAPHS] = N_NODES;
            for (int b = B_GRAPHS - 1; b >= 0; b--)
                if (rs[b] < 0) rs[b] = rs[b + 1];
            for (int b = 0; b <= B_GRAPHS; b++) d_roff[b] = rs[b];
        }
        return;
    }
    if (blk < 258) {                                // ---- wpack tile transpose ----
        float4 (*tile)[33] = reinterpret_cast<float4(*)[33]>(sraw);
        int tb = blk - 2;
        int ot = tb >> 4, it = tb & 15;             // 16x16 tiles of 32x32
        int oo = t >> 5, ii = t & 31;
        int o = ot * 32 + oo, i = it * 32 + ii;
        int idx = o * H_DIM + i;                    // coalesced read (ii fast)
        float invS = 1.0f / scale[idx];
        tile[ii][oo] = make_float4(invS, -trans[idx] * invS,
                                   MH_Cf * wavw[idx], basew[idx]);
        __syncthreads();
        int ii2 = t >> 5, oo2 = t & 31;
        d_wpack[(it * 32 + ii2) * H_DIM + (ot * 32 + oo2)] = tile[ii2][oo2]; // coalesced write
        return;
    }
    if (blk < 770) {                                // ---- h ----
        int idx = (blk - 258) * 1024 + t;           // n*H + j
        int n = idx >> 9, j = idx & 511;
        float2 p = reinterpret_cast<const float2*>(x)[n * (F_DIM / 2) + j];
        float lo = (p.x + p.y) * INV_SQRT2;
        float hi = (p.x - p.y) * INV_SQRT2;
        float s  = fsigmoid(lo * watt[0] + hi * watt[1]);
        d_h[idx] = hi + s * (lo - hi);
        return;
    }
    if (blk < 898) {                                // ---- zero d_conv ----
        int idx = (blk - 770) * 1024 + t;
        reinterpret_cast<float4*>(d_conv)[idx] = make_float4(0.f, 0.f, 0.f, 0.f);
        return;
    }
    if (blk < 930) {                                // ---- colstats over x ----
        float* ssum = reinterpret_cast<float*>(sraw);          // [32][32]
        float* ssq  = reinterpret_cast<float*>(sraw + 4096);   // [32][32]
        int c = t & 31, r = t >> 5;                 // r in 0..31
        int j = (blk - 898) * 32 + c;
        float s = 0.0f, q = 0.0f;
        for (int n = r; n < N_NODES; n += 32) {
            float v = x[n * F_DIM + j];
            s += v; q = fmaf(v, v, q);
        }
        ssum[r * 32 + c] = s; ssq[r * 32 + c] = q;
        __syncthreads();
        if (r == 0) {
#pragma unroll
            for (int rr = 1; rr < 32; rr++) { s += ssum[rr * 32 + c]; q += ssq[rr * 32 + c]; }
            float mu  = s * (1.0f / N_NODES);
            float var = fmaxf(q * (1.0f / N_NODES) - mu * mu, 0.0f);
            d_mu[j] = mu;
            d_sc[j] = rsqrtf(var + EPSB);
        }
        return;
    }
    {                                               // ---- pool sums over x ----
        int* bounds = reinterpret_cast<int*>(sraw);
        int b = blk - 930;                          // graph 0..15
        if (t == 0) {
            bounds[0] = lower_bound_batch(batch, b);
            bounds[1] = lower_bound_batch(batch, b + 1);
        }
        __syncthreads();
        int beg = bounds[0], end = bounds[1];
        int j = t;                                  // 0..1023 x columns
        float s = 0.0f;
        int n = beg;
        for (; n + 4 <= end; n += 4) {
            float v0 = x[n * F_DIM + j];
            float v1 = x[(n + 1) * F_DIM + j];
            float v2 = x[(n + 2) * F_DIM + j];
            float v3 = x[(n + 3) * F_DIM + j];
            s += (v0 + v1) + (v2 + v3);
        }
        for (; n < end; n++) s += x[n * F_DIM + j];
        d_gsum[b * Z_DIM + j] = s;
    }
}

// =================================================================================
// 2. gather: agg[n] = h[n] + sum_{e: dst=n} h[src]
// =================================================================================
__global__ void __launch_bounds__(128) k_gather() {
    __shared__ int se[128];
    int n = blockIdx.x, t = threadIdx.x;
    int beg = d_off[n], end = d_off[n + 1];
    float4 acc = reinterpret_cast<const float4*>(d_h + n * H_DIM)[t];
    for (int t0 = beg; t0 < end; t0 += 128) {
        int cnt = min(128, end - t0);
        if (t < cnt) se[t] = d_elist[t0 + t];
        __syncthreads();
        int k = 0;
        for (; k + 4 <= cnt; k += 4) {
            float4 v0 = reinterpret_cast<const float4*>(d_h + se[k]     * H_DIM)[t];
            float4 v1 = reinterpret_cast<const float4*>(d_h + se[k + 1] * H_DIM)[t];
            float4 v2 = reinterpret_cast<const float4*>(d_h + se[k + 2] * H_DIM)[t];
            float4 v3 = reinterpret_cast<const float4*>(d_h + se[k + 3] * H_DIM)[t];
            acc.x += v0.x + v1.x + v2.x + v3.x;
            acc.y += v0.y + v1.y + v2.y + v3.y;
            acc.z += v0.z + v1.z + v2.z + v3.z;
            acc.w += v0.w + v1.w + v2.w + v3.w;
        }
        for (; k < cnt; k++) {
            float4 v = reinterpret_cast<const float4*>(d_h + se[k] * H_DIM)[t];
            acc.x += v.x; acc.y += v.y; acc.z += v.z; acc.w += v.w;
        }
        __syncthreads();
    }
    reinterpret_cast<float4*>(d_agg + n * H_DIM)[t] = acc;
}

// =================================================================================
// 3. main loop: wav + base, packed f32x2, RN=16/SPLIT=16, RED into d_conv
//    grid (4, 64, 16) = 4096 blocks, 4KB smem, ~48 regs
// =================================================================================
__global__ void __launch_bounds__(128) k_wavbase() {
    __shared__ ulonglong2 s_pair[ISPLIT * NPAIR];     // [i_local][p] = {agg01, sa01}
    float* s_f = reinterpret_cast<float*>(s_pair);
    int t  = threadIdx.x;
    int o  = blockIdx.x * 128 + t;
    int n0 = blockIdx.y * RN;
    int i0 = blockIdx.z * ISPLIT;

    for (int idx = t; idx < (ISPLIT / 4) * RN; idx += 128) {
        int c = idx / RN;
        int n = idx % RN;
        float4 a4 = *reinterpret_cast<const float4*>(&d_agg[(n0 + n) * H_DIM + i0 + c * 4]);
        int p = n >> 1, half = n & 1;
        float av[4] = {a4.x, a4.y, a4.z, a4.w};
#pragma unroll
        for (int d = 0; d < 4; d++) {
            int i = c * 4 + d;
            float a  = av[d];
            float sa = a * fsigmoid(a);
            int base = (i * NPAIR + p) * 4;
            s_f[base + half]     = a;
            s_f[base + 2 + half] = sa;
        }
    }
    __syncthreads();

    u64 acc[NPAIR];
#pragma unroll
    for (int p = 0; p < NPAIR; p++) acc[p] = 0ull;
    const u64 cc2 = pack2(NEG_HALF_LOG2E, NEG_HALF_LOG2E);

    for (int i = 0; i < ISPLIT; i++) {
        float4 w = __ldg(&d_wpack[(i0 + i) * H_DIM + o]); // {invS, -T*invS, C*Ww, Wb}
        u64 wx2 = pack2(w.x, w.x);
        u64 wy2 = pack2(w.y, w.y);
        float nz = -w.z;
        u64 nwz2 = pack2(nz, nz);
        u64 wz2  = pack2(w.z, w.z);
        u64 ww2  = pack2(w.w, w.w);
        const ulonglong2* row = &s_pair[i * NPAIR];
#pragma unroll
        for (int p = 0; p < NPAIR; p++) {
            ulonglong2 v = row[p];
            u64 u   = fma2(v.x, wx2, wy2);
            u64 tt  = mul2(u, u);
            u64 arg = mul2(tt, cc2);
            float alo, ahi; unpack2(arg, alo, ahi);
            u64 e   = pack2(ex2f(alo), ex2f(ahi));
            u64 g   = fma2(tt, nwz2, wz2);
            acc[p]  = fma2(v.y, ww2, acc[p]);
            acc[p]  = fma2(g, e, acc[p]);
        }
    }
#pragma unroll
    for (int p = 0; p < NPAIR; p++) {
        float w0, w1;
        unpack2(acc[p], w0, w1);
        atomicAdd(&d_conv[(n0 + 2 * p)     * H_DIM + o], w0);
        atomicAdd(&d_conv[(n0 + 2 * p + 1) * H_DIM + o], w1);
    }
}

// =================================================================================
// 4. stats over conv columns (launch #4 — profiled), 1024-thread blocks:
//    blocks [0,15]  : colstats (32 cols x 32 node-strips) with triple-bn fold
//    blocks [16,47] : pool sums (256 cols x 4 range-strips)
// =================================================================================
__global__ void __launch_bounds__(1024) k_stats_conv() {
    __shared__ __align__(16) float sm[2 * 32 * 33];
    int blk = blockIdx.x, t = threadIdx.x;
    if (blk < 16) {                                   // ---- colstats (conv) ----
        float* ssum = sm;                             // [32][33]
        float* ssq  = sm + 32 * 33;
        int c = t & 31, r = t >> 5;                   // 32 strips
        int col = blk * 32 + c;
        int j = F_DIM + col;
        float s = 0.0f, q = 0.0f;
        for (int n = r; n < N_NODES; n += 32) {
            float v = d_conv[n * H_DIM + col];
            s += v; q = fmaf(v, v, q);
        }
        ssum[r * 33 + c] = s; ssq[r * 33 + c] = q;
        __syncthreads();
        if (r == 0) {
#pragma unroll
            for (int rr = 1; rr < 32; rr++) { s += ssum[rr * 33 + c]; q += ssq[rr * 33 + c]; }
            float mu  = s * (1.0f / N_NODES);
            float var = fmaxf(q * (1.0f / N_NODES) - mu * mu, 0.0f);
            float a1 = rsqrtf(var + EPSB);
            float v1 = var / (var + EPSB);
            float a2 = rsqrtf(v1 + EPSB);
            float v2 = v1 / (v1 + EPSB);
            float a3 = rsqrtf(v2 + EPSB);
            d_mu[j] = mu;
            d_sc[j] = a1 * a2 * a3;
        }
        return;
    }
    {                                                 // ---- pool sums (conv) ----
        float* part = sm;                             // [4][256]
        int w   = blk - 16;                           // 0..31
        int b   = w >> 1;
        int ch  = w & 1;
        int col = ch * 256 + (t & 255);
        int strip = t >> 8;                           // 0..3
        int j   = F_DIM + col;
        int beg = d_roff[b], end = d_roff[b + 1];
        float s = 0.0f;
        for (int n = beg + strip; n < end; n += 4)
            s += d_conv[n * H_DIM + col];
        part[strip * 256 + (t & 255)] = s;
        __syncthreads();
        if (strip == 0) {
            s += part[256 + (t & 255)] + part[512 + (t & 255)] + part[768 + (t & 255)];
            d_gsum[b * Z_DIM + j] = s;
        }
    }
}

// =================================================================================
// 5. poolfinal: pooled_t[j][b] = (gsum[b][j]/cnt_b - mu_j) * sc_j  (transposed)
// =================================================================================
__global__ void __launch_bounds__(1024) k_poolfinal() {
    int idx = blockIdx.x * 1024 + threadIdx.x;        // j*16 + b
    if (idx >= Z_DIM * B_GRAPHS) return;
    int j = idx >> 4, b = idx & 15;
    int c = d_roff[b + 1] - d_roff[b];
    float pooled = 0.0f;
    if (c > 0)
        pooled = (d_gsum[b * Z_DIM + j] / (float)c - d_mu[j]) * d_sc[j];
    d_pooled_t[idx] = pooled;
}

// =================================================================================
// 6. fc1 + relu: 64 blocks x 256 thr, warp-per-output, vectorized pooled_t loads
// =================================================================================
__global__ void __launch_bounds__(256) k_fc1(const float* __restrict__ w,
                                             const float* __restrict__ bias) {
    int warp = blockIdx.x * 8 + (threadIdx.x >> 5);   // 0..511 = o
    int lane = threadIdx.x & 31;
    float acc[B_GRAPHS];
#pragma unroll
    for (int b = 0; b < B_GRAPHS; b++) acc[b] = 0.0f;
    for (int k0 = 0; k0 < Z_DIM; k0 += 32) {
        int j = k0 + lane;
        float wv = w[warp * Z_DIM + j];
        const float4* pt = reinterpret_cast<const float4*>(&d_pooled_t[j * B_GRAPHS]);
#pragma unroll
        for (int qq = 0; qq < 4; qq++) {
            float4 p4 = pt[qq];
            acc[qq * 4 + 0] = fmaf(wv, p4.x, acc[qq * 4 + 0]);
            acc[qq * 4 + 1] = fmaf(wv, p4.y, acc[qq * 4 + 1]);
            acc[qq * 4 + 2] = fmaf(wv, p4.z, acc[qq * 4 + 2]);
            acc[qq * 4 + 3] = fmaf(wv, p4.w, acc[qq * 4 + 3]);
        }
    }
#pragma unroll
    for (int b = 0; b < B_GRAPHS; b++) {
        float s = acc[b];
        s += __shfl_xor_sync(0xffffffffu, s, 16);
        s += __shfl_xor_sync(0xffffffffu, s, 8);
        s += __shfl_xor_sync(0xffffffffu, s, 4);
        s += __shfl_xor_sync(0xffffffffu, s, 2);
        s += __shfl_xor_sync(0xffffffffu, s, 1);
        acc[b] = s;
    }
    if (lane == 0) {
        float bi = bias[warp];
#pragma unroll
        for (int b = 0; b < B_GRAPHS; b++)
            d_h1[b * 512 + warp] = fmaxf(acc[b] + bi, 0.0f);
    }
}

// =================================================================================
// 7. fc2: one warp per (graph, output)
// =================================================================================
__global__ void __launch_bounds__(1024) k_fc2(const float* __restrict__ w,
                                              const float* __restrict__ bias,
                                              float* __restrict__ out) {
    int gw   = (blockIdx.x * blockDim.x + threadIdx.x) >> 5;  // 0..159
    int lane = threadIdx.x & 31;
    if (gw >= B_GRAPHS * OUT_DIM) return;
    int b = gw / OUT_DIM, k = gw % OUT_DIM;
    float s = 0.0f;
#pragma unroll
    for (int i = 0; i < 512 / 32; i++) {
        int o = i * 32 + lane;
        s = fmaf(d_h1[b * 512 + o], w[k * 512 + o], s);
    }
    s += __shfl_xor_sync(0xffffffffu, s, 16);
    s += __shfl_xor_sync(0xffffffffu, s, 8);
    s += __shfl_xor_sync(0xffffffffu, s, 4);
    s += __shfl_xor_sync(0xffffffffu, s, 2);
    s += __shfl_xor_sync(0xffffffffu, s, 1);
    if (lane == 0) out[b * OUT_DIM + k] = s + bias[k];
}

// ---------------- launch ----------------------------------------------------------
extern "C" void kernel_launch(void* const* d_in, const int* in_sizes, int n_in,
                              void* d_out, int out_size) {
    const float* x      = (const float*)d_in[0];
    const float* w_att  = (const float*)d_in[1];
    const float* wscale = (const float*)d_in[2];
    const float* wtrans = (const float*)d_in[3];
    const float* wwav   = (const float*)d_in[4];
    const float* wbase  = (const float*)d_in[5];
    const float* fc1w   = (const float*)d_in[6];
    const float* fc1b   = (const float*)d_in[7];
    const float* fc2w   = (const float*)d_in[8];
    const float* fc2b   = (const float*)d_in[9];
    const int*   eidx   = (const int*)d_in[10];
    const int*   batch  = (const int*)d_in[11];
    float*       out    = (float*)d_out;

    k_setup<<<946, 1024>>>(x, w_att, wscale, wtrans, wwav, wbase, eidx, batch); // #1
    k_gather<<<N_NODES, 128>>>();                                     // #2
    k_wavbase<<<dim3(H_DIM / 128, N_NODES / RN, SPLIT), 128>>>();     // #3
    k_stats_conv<<<48, 1024>>>();                                     // #4 (profiled)
    k_poolfinal<<<24, 1024>>>();                                      // #5
    k_fc1<<<64, 256>>>(fc1w, fc1b);                                   // #6
    k_fc2<<<5, 1024>>>(fc2w, fc2b, out);                              // #7
}